// round 5
// baseline (speedup 1.0000x reference)
#include <cuda_runtime.h>

#define NEGV (-1000000000.0f)

// B=2 S=2048 D=1024 H=16 A=64
__device__ float g_qkv[(size_t)4096 * 3072];  // 48 MB scratch
__device__ float g_ctx[(size_t)4096 * 1024];  // 16 MB scratch

__device__ __forceinline__ unsigned f2tf32(float x) {
    unsigned y;
    asm("cvt.rna.tf32.f32 %0, %1;" : "=r"(y) : "f"(x));
    return y;
}

__device__ __forceinline__ void mma_tf32(float* d, const unsigned* a, const unsigned* b) {
    asm volatile(
        "mma.sync.aligned.m16n8k8.row.col.f32.tf32.tf32.f32 "
        "{%0,%1,%2,%3}, {%4,%5,%6,%7}, {%8,%9}, {%0,%1,%2,%3};"
        : "+f"(d[0]), "+f"(d[1]), "+f"(d[2]), "+f"(d[3])
        : "r"(a[0]), "r"(a[1]), "r"(a[2]), "r"(a[3]), "r"(b[0]), "r"(b[1]));
}

__device__ __forceinline__ unsigned sptr(const void* p) {
    return (unsigned)__cvta_generic_to_shared(p);
}

__device__ __forceinline__ void cpa16(unsigned s, const void* g) {
    asm volatile("cp.async.cg.shared.global [%0], [%1], 16;\n" :: "r"(s), "l"(g));
}

// ---------------------------------------------------------------------------
// TF32 SGEMM: 128x128 tile, BK=32, 256 threads (8 warps 2x4), warp 64x32.
// Round 5: 3-stage cp.async pipeline, ONE __syncthreads per k-iter.
// ---------------------------------------------------------------------------
#define APITCH 36
#define BPITCH 136
#define ASTAGE (128 * APITCH)
#define BSTAGE (32 * BPITCH)

__global__ __launch_bounds__(256, 2) void sgemm_tf32(
    const float* __restrict__ A, const float* __restrict__ B,
    const float* __restrict__ bias, float* __restrict__ C,
    int M, int N, int K)
{
    extern __shared__ float smg[];
    float* As = smg;                 // [3][128*36]
    float* Bs = smg + 3 * ASTAGE;    // [3][32*136]

    const int tid = threadIdx.x;
    const int bx = blockIdx.x, by = blockIdx.y;
    const int lane = tid & 31, wid = tid >> 5;
    const int g = lane >> 2, tig = lane & 3;
    const int wm = (wid & 1) * 64;
    const int wn = (wid >> 1) * 32;

    const int ra = tid >> 1;              // A row 0..127
    const int ca = (tid & 1) * 16;        // A col half
    const int rb = tid >> 3;              // B row 0..31
    const int cb = (tid & 7) * 16;        // B col chunk

    const float* aptr = A + (size_t)(by * 128 + ra) * K + ca;
    const float* bptr = B + (size_t)rb * N + bx * 128 + cb;

    const unsigned sa_base = sptr(&As[ra * APITCH + ca]);
    const unsigned sb_base = sptr(&Bs[rb * BPITCH + cb]);

    float acc[4][4][4];
#pragma unroll
    for (int mt = 0; mt < 4; mt++)
#pragma unroll
        for (int nt = 0; nt < 4; nt++)
#pragma unroll
            for (int i = 0; i < 4; i++) acc[mt][nt][i] = 0.0f;

    const int nt_iters = K >> 5;

    // prologue: issue stages 0 and 1
#pragma unroll
    for (int p = 0; p < 2; p++) {
        const float* ag = aptr + p * 32;
        const float* bg = bptr + (size_t)p * 32 * N;
        const unsigned sa = sa_base + p * (ASTAGE * 4);
        const unsigned sb = sb_base + p * (BSTAGE * 4);
#pragma unroll
        for (int i = 0; i < 4; i++) cpa16(sa + i * 16, ag + i * 4);
#pragma unroll
        for (int i = 0; i < 4; i++) cpa16(sb + i * 16, bg + i * 4);
        asm volatile("cp.async.commit_group;\n");
    }

    for (int t = 0; t < nt_iters; t++) {
        if (t + 1 < nt_iters)
            asm volatile("cp.async.wait_group 1;\n");
        else
            asm volatile("cp.async.wait_group 0;\n");
        __syncthreads();

        // issue stage t+2 (its buffer was consumed in iter t-1; barrier above
        // ordered that)
        if (t + 2 < nt_iters) {
            const int s = (t + 2) % 3;
            const float* ag = aptr + (t + 2) * 32;
            const float* bg = bptr + (size_t)(t + 2) * 32 * N;
            const unsigned sa = sa_base + s * (ASTAGE * 4);
            const unsigned sb = sb_base + s * (BSTAGE * 4);
#pragma unroll
            for (int i = 0; i < 4; i++) cpa16(sa + i * 16, ag + i * 4);
#pragma unroll
            for (int i = 0; i < 4; i++) cpa16(sb + i * 16, bg + i * 4);
        }
        asm volatile("cp.async.commit_group;\n");

        const float* Ab = As + (t % 3) * ASTAGE;
        const float* Bb = Bs + (t % 3) * BSTAGE;

#pragma unroll
        for (int ks = 0; ks < 4; ks++) {
            const int k0 = ks * 8;
            unsigned af[4][4], bf[4][2];
#pragma unroll
            for (int mt = 0; mt < 4; mt++) {
                int r0 = wm + mt * 16 + g;
                af[mt][0] = f2tf32(Ab[r0 * APITCH + k0 + tig]);
                af[mt][1] = f2tf32(Ab[(r0 + 8) * APITCH + k0 + tig]);
                af[mt][2] = f2tf32(Ab[r0 * APITCH + k0 + tig + 4]);
                af[mt][3] = f2tf32(Ab[(r0 + 8) * APITCH + k0 + tig + 4]);
            }
#pragma unroll
            for (int nt = 0; nt < 4; nt++) {
                int c0 = wn + nt * 8 + g;
                bf[nt][0] = f2tf32(Bb[(k0 + tig) * BPITCH + c0]);
                bf[nt][1] = f2tf32(Bb[(k0 + tig + 4) * BPITCH + c0]);
            }
#pragma unroll
            for (int mt = 0; mt < 4; mt++)
#pragma unroll
                for (int nt = 0; nt < 4; nt++)
                    mma_tf32(acc[mt][nt], af[mt], bf[nt]);
        }
    }

    float bv0[4], bv1[4];
#pragma unroll
    for (int nt = 0; nt < 4; nt++) { bv0[nt] = 0.0f; bv1[nt] = 0.0f; }
    if (bias) {
#pragma unroll
        for (int nt = 0; nt < 4; nt++) {
            int col = bx * 128 + wn + nt * 8 + 2 * tig;
            bv0[nt] = bias[col];
            bv1[nt] = bias[col + 1];
        }
    }

#pragma unroll
    for (int mt = 0; mt < 4; mt++) {
        int row = by * 128 + wm + mt * 16 + g;
#pragma unroll
        for (int nt = 0; nt < 4; nt++) {
            int col = bx * 128 + wn + nt * 8 + 2 * tig;
            float2 s0, s1;
            s0.x = acc[mt][nt][0] + bv0[nt];
            s0.y = acc[mt][nt][1] + bv1[nt];
            s1.x = acc[mt][nt][2] + bv0[nt];
            s1.y = acc[mt][nt][3] + bv1[nt];
            *(float2*)(C + (size_t)row * N + col) = s0;
            *(float2*)(C + (size_t)(row + 8) * N + col) = s1;
        }
    }
}

// ---------------------------------------------------------------------------
// Tensor-core flash attention, round 5:
//  - cp.async double-buffered K/V/mask (raw fp32 in smem, cvt.rna at frag load)
//  - one __syncthreads per tile; copy of tile t+1 overlaps compute of tile t
//  - 2 CTAs/SM target (launch_bounds(256,2))
// ---------------------------------------------------------------------------
#define QP 68
#define VP 72
#define KSTG (64 * QP)
#define VSTG (64 * VP)

__global__ __launch_bounds__(256, 2) void attn_tc(
    const float* __restrict__ qkv, const int* __restrict__ mask,
    float* __restrict__ ctx)
{
    extern __shared__ float smf[];
    float* Qf = smf;                          // [128][68] fp32->tf32 (aliased by Ps)
    float* Kf = smf + 128 * QP;               // [2][64][68] raw fp32
    float* Vf = Kf + 2 * KSTG;                // [2][64][72] raw fp32
    int*   Mk = (int*)(Vf + 2 * VSTG);        // [2][64]
    unsigned* Qu = (unsigned*)Qf;
    unsigned* Ps = Qu;                        // alias: Q consumed before first P write

    const int tid = threadIdx.x;
    const int lane = tid & 31, wid = tid >> 5;
    const int g = lane >> 2, tig = lane & 3;
    const int W = wid * 16;

    const int q0 = blockIdx.x * 128;
    const int h  = blockIdx.y;
    const int b  = blockIdx.z;
    const size_t baseRow = (size_t)b * 2048;

    // ---- prologue: Q tile -> smem (tf32) -> registers ----
#pragma unroll
    for (int i = 0; i < 8; i++) {
        int lin = tid + 256 * i;
        int r = lin >> 4, a4 = lin & 15;
        float4 v = *(const float4*)(qkv + (baseRow + q0 + r) * 3072 + h * 64 + a4 * 4);
        uint4 u;
        u.x = f2tf32(v.x); u.y = f2tf32(v.y); u.z = f2tf32(v.z); u.w = f2tf32(v.w);
        *(uint4*)&Qu[r * QP + a4 * 4] = u;
    }
    __syncthreads();

    unsigned qa[8][4];
#pragma unroll
    for (int ks = 0; ks < 8; ks++) {
        qa[ks][0] = Qu[(W + g) * QP + ks * 8 + tig];
        qa[ks][1] = Qu[(W + g + 8) * QP + ks * 8 + tig];
        qa[ks][2] = Qu[(W + g) * QP + ks * 8 + tig + 4];
        qa[ks][3] = Qu[(W + g + 8) * QP + ks * 8 + tig + 4];
    }
    __syncthreads();  // Q fully consumed; Ps may now overwrite Qf

    // cp.async loader mapping: 256 threads, each 4 rows' quarter per buffer
    const int kr = tid >> 2;          // row 0..63
    const int kc = (tid & 3) * 16;    // col chunk (16 floats)

    // issue tile 0
    {
        const float* src = qkv + (baseRow + kr) * 3072 + h * 64 + kc;
        unsigned sk = sptr(&Kf[kr * QP + kc]);
        unsigned sv = sptr(&Vf[kr * VP + kc]);
#pragma unroll
        for (int i = 0; i < 4; i++) cpa16(sk + i * 16, src + 1024 + i * 4);
#pragma unroll
        for (int i = 0; i < 4; i++) cpa16(sv + i * 16, src + 2048 + i * 4);
        if (tid < 16) cpa16(sptr(&Mk[tid * 4]), mask + b * 2048 + tid * 4);
        asm volatile("cp.async.commit_group;\n");
    }

    float O[8][4];
#pragma unroll
    for (int nt = 0; nt < 8; nt++)
#pragma unroll
        for (int i = 0; i < 4; i++) O[nt][i] = 0.0f;
    float mA = -1e30f, mB = -1e30f, lA = 0.0f, lB = 0.0f;

    for (int t = 0; t < 32; t++) {
        asm volatile("cp.async.wait_group 0;\n");
        __syncthreads();  // tile t visible to all; buffer (t+1)&1 free (read at t-1)

        // issue tile t+1 into the other buffer; overlaps compute of tile t
        if (t + 1 < 32) {
            const int s = (t + 1) & 1;
            const float* src = qkv + (baseRow + (t + 1) * 64 + kr) * 3072 + h * 64 + kc;
            unsigned sk = sptr(&Kf[s * KSTG + kr * QP + kc]);
            unsigned sv = sptr(&Vf[s * VSTG + kr * VP + kc]);
#pragma unroll
            for (int i = 0; i < 4; i++) cpa16(sk + i * 16, src + 1024 + i * 4);
#pragma unroll
            for (int i = 0; i < 4; i++) cpa16(sv + i * 16, src + 2048 + i * 4);
            if (tid < 16) cpa16(sptr(&Mk[s * 64 + tid * 4]),
                                mask + b * 2048 + (t + 1) * 64 + tid * 4);
            asm volatile("cp.async.commit_group;\n");
        }

        const float* Kb = Kf + (t & 1) * KSTG;
        const float* Vb = Vf + (t & 1) * VSTG;
        const int*   Mb = Mk + (t & 1) * 64;

        // ---- S = Q K^T ----
        float s[8][4];
#pragma unroll
        for (int nt = 0; nt < 8; nt++)
#pragma unroll
            for (int i = 0; i < 4; i++) s[nt][i] = 0.0f;

#pragma unroll
        for (int nt = 0; nt < 8; nt++) {
            const int key = nt * 8 + g;
#pragma unroll
            for (int ks = 0; ks < 8; ks++) {
                unsigned bf[2];
                bf[0] = f2tf32(Kb[key * QP + ks * 8 + tig]);
                bf[1] = f2tf32(Kb[key * QP + ks * 8 + tig + 4]);
                mma_tf32(s[nt], qa[ks], bf);
            }
        }

        // ---- mask + online softmax (fragment layout) ----
        float mxA = -1e30f, mxB = -1e30f;
#pragma unroll
        for (int nt = 0; nt < 8; nt++) {
            const int c = nt * 8 + 2 * tig;
            const int m0 = Mb[c], m1 = Mb[c + 1];
            s[nt][0] = (m0 == 0) ? NEGV : s[nt][0] * 0.125f;
            s[nt][1] = (m1 == 0) ? NEGV : s[nt][1] * 0.125f;
            s[nt][2] = (m0 == 0) ? NEGV : s[nt][2] * 0.125f;
            s[nt][3] = (m1 == 0) ? NEGV : s[nt][3] * 0.125f;
            mxA = fmaxf(mxA, fmaxf(s[nt][0], s[nt][1]));
            mxB = fmaxf(mxB, fmaxf(s[nt][2], s[nt][3]));
        }
        mxA = fmaxf(mxA, __shfl_xor_sync(0xffffffffu, mxA, 1));
        mxA = fmaxf(mxA, __shfl_xor_sync(0xffffffffu, mxA, 2));
        mxB = fmaxf(mxB, __shfl_xor_sync(0xffffffffu, mxB, 1));
        mxB = fmaxf(mxB, __shfl_xor_sync(0xffffffffu, mxB, 2));

        const float mnA = fmaxf(mA, mxA);
        const float mnB = fmaxf(mB, mxB);
        const float alphaA = __expf(mA - mnA);
        const float alphaB = __expf(mB - mnB);
        float sumA = 0.0f, sumB = 0.0f;
#pragma unroll
        for (int nt = 0; nt < 8; nt++) {
            s[nt][0] = __expf(s[nt][0] - mnA);
            s[nt][1] = __expf(s[nt][1] - mnA);
            s[nt][2] = __expf(s[nt][2] - mnB);
            s[nt][3] = __expf(s[nt][3] - mnB);
            sumA += s[nt][0] + s[nt][1];
            sumB += s[nt][2] + s[nt][3];
        }
        sumA += __shfl_xor_sync(0xffffffffu, sumA, 1);
        sumA += __shfl_xor_sync(0xffffffffu, sumA, 2);
        sumB += __shfl_xor_sync(0xffffffffu, sumB, 1);
        sumB += __shfl_xor_sync(0xffffffffu, sumB, 2);
        lA = lA * alphaA + sumA;  mA = mnA;
        lB = lB * alphaB + sumB;  mB = mnB;
#pragma unroll
        for (int nt = 0; nt < 8; nt++) {
            O[nt][0] *= alphaA; O[nt][1] *= alphaA;
            O[nt][2] *= alphaB; O[nt][3] *= alphaB;
        }

        // ---- P -> smem (tf32, A-layout); warp-local rows ----
#pragma unroll
        for (int nt = 0; nt < 8; nt++) {
            const int c = nt * 8 + 2 * tig;
            Ps[(W + g) * QP + c]     = f2tf32(s[nt][0]);
            Ps[(W + g) * QP + c + 1] = f2tf32(s[nt][1]);
            Ps[(W + g + 8) * QP + c]     = f2tf32(s[nt][2]);
            Ps[(W + g + 8) * QP + c + 1] = f2tf32(s[nt][3]);
        }
        __syncwarp();

        unsigned pa[8][4];
#pragma unroll
        for (int ks = 0; ks < 8; ks++) {
            pa[ks][0] = Ps[(W + g) * QP + ks * 8 + tig];
            pa[ks][1] = Ps[(W + g + 8) * QP + ks * 8 + tig];
            pa[ks][2] = Ps[(W + g) * QP + ks * 8 + tig + 4];
            pa[ks][3] = Ps[(W + g + 8) * QP + ks * 8 + tig + 4];
        }

        // ---- O += P V ----
#pragma unroll
        for (int nt = 0; nt < 8; nt++) {
            const int d = nt * 8 + g;
#pragma unroll
            for (int ks = 0; ks < 8; ks++) {
                unsigned bf[2];
                bf[0] = f2tf32(Vb[(ks * 8 + tig) * VP + d]);
                bf[1] = f2tf32(Vb[(ks * 8 + tig + 4) * VP + d]);
                mma_tf32(O[nt], pa[ks], bf);
            }
        }
    }

    const float invA = 1.0f / lA;
    const float invB = 1.0f / lB;
    const size_t rowA = baseRow + q0 + W + g;
#pragma unroll
    for (int nt = 0; nt < 8; nt++) {
        const int col = h * 64 + nt * 8 + 2 * tig;
        float2 oA, oB;
        oA.x = O[nt][0] * invA; oA.y = O[nt][1] * invA;
        oB.x = O[nt][2] * invB; oB.y = O[nt][3] * invB;
        *(float2*)(ctx + rowA * 1024 + col) = oA;
        *(float2*)(ctx + (rowA + 8) * 1024 + col) = oB;
    }
}

// ---------------------------------------------------------------------------
extern "C" void kernel_launch(void* const* d_in, const int* in_sizes, int n_in,
                              void* d_out, int out_size)
{
    const float* qs   = (const float*)d_in[0];
    const int*   mask = (const int*)d_in[1];
    const float* Wqkv = (const float*)d_in[2];
    const float* Wout = (const float*)d_in[3];
    const float* bout = (const float*)d_in[4];
    float* out = (float*)d_out;

    float *qkvP, *ctxP;
    cudaGetSymbolAddress((void**)&qkvP, g_qkv);
    cudaGetSymbolAddress((void**)&ctxP, g_ctx);

    const int gemmSmem = 3 * (ASTAGE + BSTAGE) * 4;  // 107520 B
    cudaFuncSetAttribute(sgemm_tf32,
                         cudaFuncAttributeMaxDynamicSharedMemorySize, gemmSmem);

    const int attnSmem = (128 * QP + 2 * KSTG + 2 * VSTG + 2 * 64) * 4;  // 107008 B
    cudaFuncSetAttribute(attn_tc,
                         cudaFuncAttributeMaxDynamicSharedMemorySize, attnSmem);

    // 1) qkv = qs @ Wqkv              [4096,1024] x [1024,3072]
    sgemm_tf32<<<dim3(24, 32), 256, gemmSmem>>>(qs, Wqkv, nullptr, qkvP, 4096, 3072, 1024);

    // 2) fused masked attention -> ctx [B,S,H*A]
    attn_tc<<<dim3(16, 16, 2), 256, attnSmem>>>(qkvP, mask, ctxP);

    // 3) out = ctx @ Wout + bout      [4096,1024] x [1024,1024]
    sgemm_tf32<<<dim3(8, 32), 256, gemmSmem>>>(ctxP, Wout, bout, out, 4096, 1024, 1024);
}

// round 6
// speedup vs baseline: 1.0738x; 1.0738x over previous
#include <cuda_runtime.h>

#define NEGV (-1000000000.0f)

// B=2 S=2048 D=1024 H=16 A=64
// All intermediates stored as tf32 bit patterns (unsigned).
__device__ unsigned g_qkv[(size_t)4096 * 3072];   // 48 MB
__device__ unsigned g_ctx[(size_t)4096 * 1024];   // 16 MB
__device__ unsigned g_qsT[(size_t)4096 * 1024];   // 16 MB
__device__ unsigned g_wqkvT[(size_t)1024 * 3072]; // 12 MB
__device__ unsigned g_woutT[(size_t)1024 * 1024]; //  4 MB

__device__ __forceinline__ unsigned f2tf32(float x) {
    unsigned y;
    asm("cvt.rna.tf32.f32 %0, %1;" : "=r"(y) : "f"(x));
    return y;
}

__device__ __forceinline__ void mma_tf32(float* d, const unsigned* a, const unsigned* b) {
    asm volatile(
        "mma.sync.aligned.m16n8k8.row.col.f32.tf32.tf32.f32 "
        "{%0,%1,%2,%3}, {%4,%5,%6,%7}, {%8,%9}, {%0,%1,%2,%3};"
        : "+f"(d[0]), "+f"(d[1]), "+f"(d[2]), "+f"(d[3])
        : "r"(a[0]), "r"(a[1]), "r"(a[2]), "r"(a[3]), "r"(b[0]), "r"(b[1]));
}

__device__ __forceinline__ unsigned sptr(const void* p) {
    return (unsigned)__cvta_generic_to_shared(p);
}

__device__ __forceinline__ void cpa16(unsigned s, const void* g) {
    asm volatile("cp.async.cg.shared.global [%0], [%1], 16;\n" :: "r"(s), "l"(g));
}

// ---------------------------------------------------------------------------
// Elementwise fp32 -> tf32-bits conversion (vectorized)
// ---------------------------------------------------------------------------
__global__ __launch_bounds__(256) void cvt_tf32_kernel(
    const float4* __restrict__ src, uint4* __restrict__ dst, int n4)
{
    int i = blockIdx.x * 256 + threadIdx.x;
    if (i < n4) {
        float4 v = src[i];
        uint4 u;
        u.x = f2tf32(v.x); u.y = f2tf32(v.y);
        u.z = f2tf32(v.z); u.w = f2tf32(v.w);
        dst[i] = u;
    }
}

// ---------------------------------------------------------------------------
// TF32 SGEMM on pre-converted tf32-bit operands. Round-4 proven pipeline:
// 2-stage cp.async double buffer, 128x128 tile, BK=32, 8 warps (2x4), 64x32
// warp tile. No cvt in the hot loop. writeTf32: C written as tf32 bits
// (intermediate) vs fp32+bias (final output).
// ---------------------------------------------------------------------------
#define APITCH 36
#define BPITCH 136
#define ASTAGE (128 * APITCH)
#define BSTAGE (32 * BPITCH)

__global__ __launch_bounds__(256, 2) void sgemm_tf32(
    const unsigned* __restrict__ A, const unsigned* __restrict__ B,
    const float* __restrict__ bias, void* __restrict__ Cout,
    int M, int N, int K, int writeTf32)
{
    extern __shared__ unsigned smg[];
    unsigned* As = smg;                 // [2][128*36]
    unsigned* Bs = smg + 2 * ASTAGE;    // [2][32*136]

    const int tid = threadIdx.x;
    const int bx = blockIdx.x, by = blockIdx.y;
    const int lane = tid & 31, wid = tid >> 5;
    const int g = lane >> 2, tig = lane & 3;
    const int wm = (wid & 1) * 64;
    const int wn = (wid >> 1) * 32;

    const int ra = tid >> 1;              // A row 0..127
    const int ca = (tid & 1) * 16;        // A col half
    const int rb = tid >> 3;              // B row 0..31
    const int cb = (tid & 7) * 16;        // B col chunk

    const unsigned* aptr = A + (size_t)(by * 128 + ra) * K + ca;
    const unsigned* bptr = B + (size_t)rb * N + bx * 128 + cb;

    const unsigned sa_base = sptr(&As[ra * APITCH + ca]);
    const unsigned sb_base = sptr(&Bs[rb * BPITCH + cb]);

    float acc[4][4][4];
#pragma unroll
    for (int mt = 0; mt < 4; mt++)
#pragma unroll
        for (int nt = 0; nt < 4; nt++)
#pragma unroll
            for (int i = 0; i < 4; i++) acc[mt][nt][i] = 0.0f;

    const int nt_iters = K >> 5;

    // issue stage 0
    {
#pragma unroll
        for (int i = 0; i < 4; i++) cpa16(sa_base + i * 16, aptr + i * 4);
#pragma unroll
        for (int i = 0; i < 4; i++) cpa16(sb_base + i * 16, bptr + i * 4);
        asm volatile("cp.async.commit_group;\n");
    }

    for (int t = 0; t < nt_iters; t++) {
        if (t + 1 < nt_iters) {
            const int s = (t + 1) & 1;
            const unsigned* ag = aptr + (t + 1) * 32;
            const unsigned* bg = bptr + (size_t)(t + 1) * 32 * N;
            const unsigned sa = sa_base + s * (ASTAGE * 4);
            const unsigned sb = sb_base + s * (BSTAGE * 4);
#pragma unroll
            for (int i = 0; i < 4; i++) cpa16(sa + i * 16, ag + i * 4);
#pragma unroll
            for (int i = 0; i < 4; i++) cpa16(sb + i * 16, bg + i * 4);
            asm volatile("cp.async.commit_group;\n");
            asm volatile("cp.async.wait_group 1;\n");
        } else {
            asm volatile("cp.async.wait_group 0;\n");
        }
        __syncthreads();

        const unsigned* Ab = As + (t & 1) * ASTAGE;
        const unsigned* Bb = Bs + (t & 1) * BSTAGE;

#pragma unroll
        for (int ks = 0; ks < 4; ks++) {
            const int k0 = ks * 8;
            unsigned af[4][4], bf[4][2];
#pragma unroll
            for (int mt = 0; mt < 4; mt++) {
                int r0 = wm + mt * 16 + g;
                af[mt][0] = Ab[r0 * APITCH + k0 + tig];
                af[mt][1] = Ab[(r0 + 8) * APITCH + k0 + tig];
                af[mt][2] = Ab[r0 * APITCH + k0 + tig + 4];
                af[mt][3] = Ab[(r0 + 8) * APITCH + k0 + tig + 4];
            }
#pragma unroll
            for (int nt = 0; nt < 4; nt++) {
                int c0 = wn + nt * 8 + g;
                bf[nt][0] = Bb[(k0 + tig) * BPITCH + c0];
                bf[nt][1] = Bb[(k0 + tig + 4) * BPITCH + c0];
            }
#pragma unroll
            for (int mt = 0; mt < 4; mt++)
#pragma unroll
                for (int nt = 0; nt < 4; nt++)
                    mma_tf32(acc[mt][nt], af[mt], bf[nt]);
        }
        __syncthreads();
    }

    if (writeTf32) {
        unsigned* C = (unsigned*)Cout;
#pragma unroll
        for (int mt = 0; mt < 4; mt++) {
            int row = by * 128 + wm + mt * 16 + g;
#pragma unroll
            for (int nt = 0; nt < 4; nt++) {
                int col = bx * 128 + wn + nt * 8 + 2 * tig;
                uint2 s0, s1;
                s0.x = f2tf32(acc[mt][nt][0]); s0.y = f2tf32(acc[mt][nt][1]);
                s1.x = f2tf32(acc[mt][nt][2]); s1.y = f2tf32(acc[mt][nt][3]);
                *(uint2*)(C + (size_t)row * N + col) = s0;
                *(uint2*)(C + (size_t)(row + 8) * N + col) = s1;
            }
        }
    } else {
        float* C = (float*)Cout;
        float bv0[4], bv1[4];
#pragma unroll
        for (int nt = 0; nt < 4; nt++) {
            int col = bx * 128 + wn + nt * 8 + 2 * tig;
            bv0[nt] = bias ? bias[col] : 0.0f;
            bv1[nt] = bias ? bias[col + 1] : 0.0f;
        }
#pragma unroll
        for (int mt = 0; mt < 4; mt++) {
            int row = by * 128 + wm + mt * 16 + g;
#pragma unroll
            for (int nt = 0; nt < 4; nt++) {
                int col = bx * 128 + wn + nt * 8 + 2 * tig;
                float2 s0, s1;
                s0.x = acc[mt][nt][0] + bv0[nt];
                s0.y = acc[mt][nt][1] + bv1[nt];
                s1.x = acc[mt][nt][2] + bv0[nt];
                s1.y = acc[mt][nt][3] + bv1[nt];
                *(float2*)(C + (size_t)row * N + col) = s0;
                *(float2*)(C + (size_t)(row + 8) * N + col) = s1;
            }
        }
    }
}

// ---------------------------------------------------------------------------
// Tensor-core flash attention (round-4 proven structure), qkv already tf32
// bits -> no cvt on Q/K/V loads. ctx written as tf32 bits for gemm2.
// ---------------------------------------------------------------------------
#define QP 68
#define VP 72

__global__ __launch_bounds__(256, 1) void attn_tc(
    const unsigned* __restrict__ qkv, const int* __restrict__ mask,
    unsigned* __restrict__ ctx)
{
    extern __shared__ unsigned sm[];
    unsigned* Qf = sm;                       // [128][68]  (aliased by Ps)
    unsigned* Kf = sm + 128 * QP;            // [64 keys][68 dims]
    unsigned* Vf = Kf + 64 * QP;             // [64 keys][72 dims]
    float*    Mk = (float*)(Vf + 64 * VP);   // [64]
    unsigned* Ps = Qf;

    const int tid = threadIdx.x;
    const int lane = tid & 31, wid = tid >> 5;
    const int g = lane >> 2, tig = lane & 3;
    const int W = wid * 16;

    const int q0 = blockIdx.x * 128;
    const int h  = blockIdx.y;
    const int b  = blockIdx.z;
    const size_t baseRow = (size_t)b * 2048;

#pragma unroll
    for (int i = 0; i < 8; i++) {
        int lin = tid + 256 * i;
        int r = lin >> 4, a4 = lin & 15;
        uint4 v = *(const uint4*)(qkv + (baseRow + q0 + r) * 3072 + h * 64 + a4 * 4);
        *(uint4*)&Qf[r * QP + a4 * 4] = v;
    }
    __syncthreads();

    unsigned qa[8][4];
#pragma unroll
    for (int ks = 0; ks < 8; ks++) {
        qa[ks][0] = Qf[(W + g) * QP + ks * 8 + tig];
        qa[ks][1] = Qf[(W + g + 8) * QP + ks * 8 + tig];
        qa[ks][2] = Qf[(W + g) * QP + ks * 8 + tig + 4];
        qa[ks][3] = Qf[(W + g + 8) * QP + ks * 8 + tig + 4];
    }
    __syncthreads();  // Q fully consumed; Ps may now overwrite Qf

    float O[8][4];
#pragma unroll
    for (int nt = 0; nt < 8; nt++)
#pragma unroll
        for (int i = 0; i < 4; i++) O[nt][i] = 0.0f;
    float mA = -1e30f, mB = -1e30f, lA = 0.0f, lB = 0.0f;

    for (int t = 0; t < 32; t++) {
        const int k0g = t * 64;
        __syncthreads();

#pragma unroll
        for (int i = 0; i < 4; i++) {
            int lin = tid + 256 * i;
            int key = lin >> 4, a4 = lin & 15;
            const unsigned* src = qkv + (baseRow + k0g + key) * 3072 + h * 64;
            uint4 kv = *(const uint4*)(src + 1024 + a4 * 4);
            *(uint4*)&Kf[key * QP + a4 * 4] = kv;
            uint4 vv = *(const uint4*)(src + 2048 + a4 * 4);
            *(uint4*)&Vf[key * VP + a4 * 4] = vv;
        }
        if (tid < 64) Mk[tid] = (float)mask[b * 2048 + k0g + tid];
        __syncthreads();

        float s[8][4];
#pragma unroll
        for (int nt = 0; nt < 8; nt++)
#pragma unroll
            for (int i = 0; i < 4; i++) s[nt][i] = 0.0f;

#pragma unroll
        for (int nt = 0; nt < 8; nt++) {
            const int key = nt * 8 + g;
#pragma unroll
            for (int ks = 0; ks < 8; ks++) {
                unsigned bf[2];
                bf[0] = Kf[key * QP + ks * 8 + tig];
                bf[1] = Kf[key * QP + ks * 8 + tig + 4];
                mma_tf32(s[nt], qa[ks], bf);
            }
        }

        float mxA = -1e30f, mxB = -1e30f;
#pragma unroll
        for (int nt = 0; nt < 8; nt++) {
            const int c = nt * 8 + 2 * tig;
            const float m0 = Mk[c], m1 = Mk[c + 1];
            s[nt][0] = (m0 == 0.0f) ? NEGV : s[nt][0] * 0.125f;
            s[nt][1] = (m1 == 0.0f) ? NEGV : s[nt][1] * 0.125f;
            s[nt][2] = (m0 == 0.0f) ? NEGV : s[nt][2] * 0.125f;
            s[nt][3] = (m1 == 0.0f) ? NEGV : s[nt][3] * 0.125f;
            mxA = fmaxf(mxA, fmaxf(s[nt][0], s[nt][1]));
            mxB = fmaxf(mxB, fmaxf(s[nt][2], s[nt][3]));
        }
        mxA = fmaxf(mxA, __shfl_xor_sync(0xffffffffu, mxA, 1));
        mxA = fmaxf(mxA, __shfl_xor_sync(0xffffffffu, mxA, 2));
        mxB = fmaxf(mxB, __shfl_xor_sync(0xffffffffu, mxB, 1));
        mxB = fmaxf(mxB, __shfl_xor_sync(0xffffffffu, mxB, 2));

        const float mnA = fmaxf(mA, mxA);
        const float mnB = fmaxf(mB, mxB);
        const float alphaA = __expf(mA - mnA);
        const float alphaB = __expf(mB - mnB);
        float sumA = 0.0f, sumB = 0.0f;
#pragma unroll
        for (int nt = 0; nt < 8; nt++) {
            s[nt][0] = __expf(s[nt][0] - mnA);
            s[nt][1] = __expf(s[nt][1] - mnA);
            s[nt][2] = __expf(s[nt][2] - mnB);
            s[nt][3] = __expf(s[nt][3] - mnB);
            sumA += s[nt][0] + s[nt][1];
            sumB += s[nt][2] + s[nt][3];
        }
        sumA += __shfl_xor_sync(0xffffffffu, sumA, 1);
        sumA += __shfl_xor_sync(0xffffffffu, sumA, 2);
        sumB += __shfl_xor_sync(0xffffffffu, sumB, 1);
        sumB += __shfl_xor_sync(0xffffffffu, sumB, 2);
        lA = lA * alphaA + sumA;  mA = mnA;
        lB = lB * alphaB + sumB;  mB = mnB;
#pragma unroll
        for (int nt = 0; nt < 8; nt++) {
            O[nt][0] *= alphaA; O[nt][1] *= alphaA;
            O[nt][2] *= alphaB; O[nt][3] *= alphaB;
        }

#pragma unroll
        for (int nt = 0; nt < 8; nt++) {
            const int c = nt * 8 + 2 * tig;
            Ps[(W + g) * QP + c]     = f2tf32(s[nt][0]);
            Ps[(W + g) * QP + c + 1] = f2tf32(s[nt][1]);
            Ps[(W + g + 8) * QP + c]     = f2tf32(s[nt][2]);
            Ps[(W + g + 8) * QP + c + 1] = f2tf32(s[nt][3]);
        }
        __syncwarp();

        unsigned pa[8][4];
#pragma unroll
        for (int ks = 0; ks < 8; ks++) {
            pa[ks][0] = Ps[(W + g) * QP + ks * 8 + tig];
            pa[ks][1] = Ps[(W + g + 8) * QP + ks * 8 + tig];
            pa[ks][2] = Ps[(W + g) * QP + ks * 8 + tig + 4];
            pa[ks][3] = Ps[(W + g + 8) * QP + ks * 8 + tig + 4];
        }

#pragma unroll
        for (int nt = 0; nt < 8; nt++) {
            const int d = nt * 8 + g;
#pragma unroll
            for (int ks = 0; ks < 8; ks++) {
                unsigned bf[2];
                bf[0] = Vf[(ks * 8 + tig) * VP + d];
                bf[1] = Vf[(ks * 8 + tig + 4) * VP + d];
                mma_tf32(O[nt], pa[ks], bf);
            }
        }
    }

    // epilogue: ctx stored as tf32 bits (gemm2 consumes them directly)
    const float invA = 1.0f / lA;
    const float invB = 1.0f / lB;
    const size_t rowA = baseRow + q0 + W + g;
#pragma unroll
    for (int nt = 0; nt < 8; nt++) {
        const int col = h * 64 + nt * 8 + 2 * tig;
        uint2 oA, oB;
        oA.x = f2tf32(O[nt][0] * invA); oA.y = f2tf32(O[nt][1] * invA);
        oB.x = f2tf32(O[nt][2] * invB); oB.y = f2tf32(O[nt][3] * invB);
        *(uint2*)(ctx + rowA * 1024 + col) = oA;
        *(uint2*)(ctx + (rowA + 8) * 1024 + col) = oB;
    }
}

// ---------------------------------------------------------------------------
extern "C" void kernel_launch(void* const* d_in, const int* in_sizes, int n_in,
                              void* d_out, int out_size)
{
    const float* qs   = (const float*)d_in[0];
    const int*   mask = (const int*)d_in[1];
    const float* Wqkv = (const float*)d_in[2];
    const float* Wout = (const float*)d_in[3];
    const float* bout = (const float*)d_in[4];
    float* out = (float*)d_out;

    unsigned *qkvP, *ctxP, *qsT, *wqkvT, *woutT;
    cudaGetSymbolAddress((void**)&qkvP,  g_qkv);
    cudaGetSymbolAddress((void**)&ctxP,  g_ctx);
    cudaGetSymbolAddress((void**)&qsT,   g_qsT);
    cudaGetSymbolAddress((void**)&wqkvT, g_wqkvT);
    cudaGetSymbolAddress((void**)&woutT, g_woutT);

    const int gemmSmem = 2 * (ASTAGE + BSTAGE) * 4;  // 71680 B
    cudaFuncSetAttribute(sgemm_tf32,
                         cudaFuncAttributeMaxDynamicSharedMemorySize, gemmSmem);

    const int attnSmem = (128 * QP + 64 * QP + 64 * VP + 64) * 4;  // 70912 B
    cudaFuncSetAttribute(attn_tc,
                         cudaFuncAttributeMaxDynamicSharedMemorySize, attnSmem);

    // 0) pre-convert inputs to tf32 bits
    cvt_tf32_kernel<<<(4096 * 1024 / 4 + 255) / 256, 256>>>(
        (const float4*)qs, (uint4*)qsT, 4096 * 1024 / 4);
    cvt_tf32_kernel<<<(1024 * 3072 / 4 + 255) / 256, 256>>>(
        (const float4*)Wqkv, (uint4*)wqkvT, 1024 * 3072 / 4);
    cvt_tf32_kernel<<<(1024 * 1024 / 4 + 255) / 256, 256>>>(
        (const float4*)Wout, (uint4*)woutT, 1024 * 1024 / 4);

    // 1) qkv(tf32 bits) = qs @ Wqkv
    sgemm_tf32<<<dim3(24, 32), 256, gemmSmem>>>(
        qsT, wqkvT, nullptr, qkvP, 4096, 3072, 1024, 1);

    // 2) fused masked attention -> ctx (tf32 bits)
    attn_tc<<<dim3(16, 16, 2), 256, attnSmem>>>(qkvP, mask, ctxP);

    // 3) out = ctx @ Wout + bout  (fp32 final)
    sgemm_tf32<<<dim3(8, 32), 256, gemmSmem>>>(
        ctxP, woutT, bout, out, 4096, 1024, 1024, 0);
}

// round 7
// speedup vs baseline: 1.1315x; 1.0537x over previous
#include <cuda_runtime.h>

#define NEGV (-1000000000.0f)

// B=2 S=2048 D=1024 H=16 A=64
// All intermediates stored as tf32 bit patterns (unsigned).
__device__ unsigned g_qkv[(size_t)4096 * 3072];   // 48 MB
__device__ unsigned g_ctx[(size_t)4096 * 1024];   // 16 MB
__device__ unsigned g_qsT[(size_t)4096 * 1024];   // 16 MB
__device__ unsigned g_wqkvT[(size_t)1024 * 3072]; // 12 MB
__device__ unsigned g_woutT[(size_t)1024 * 1024]; //  4 MB

__device__ __forceinline__ unsigned f2tf32(float x) {
    unsigned y;
    asm("cvt.rna.tf32.f32 %0, %1;" : "=r"(y) : "f"(x));
    return y;
}

__device__ __forceinline__ void mma_tf32(float* d, const unsigned* a, const unsigned* b) {
    asm volatile(
        "mma.sync.aligned.m16n8k8.row.col.f32.tf32.tf32.f32 "
        "{%0,%1,%2,%3}, {%4,%5,%6,%7}, {%8,%9}, {%0,%1,%2,%3};"
        : "+f"(d[0]), "+f"(d[1]), "+f"(d[2]), "+f"(d[3])
        : "r"(a[0]), "r"(a[1]), "r"(a[2]), "r"(a[3]), "r"(b[0]), "r"(b[1]));
}

__device__ __forceinline__ unsigned sptr(const void* p) {
    return (unsigned)__cvta_generic_to_shared(p);
}

__device__ __forceinline__ void cpa16(unsigned s, const void* g) {
    asm volatile("cp.async.cg.shared.global [%0], [%1], 16;\n" :: "r"(s), "l"(g));
}

// ---------------------------------------------------------------------------
// Elementwise fp32 -> tf32-bits conversion (vectorized)
// ---------------------------------------------------------------------------
__global__ __launch_bounds__(256) void cvt_tf32_kernel(
    const float4* __restrict__ src, uint4* __restrict__ dst, int n4)
{
    int i = blockIdx.x * 256 + threadIdx.x;
    if (i < n4) {
        float4 v = src[i];
        uint4 u;
        u.x = f2tf32(v.x); u.y = f2tf32(v.y);
        u.z = f2tf32(v.z); u.w = f2tf32(v.w);
        dst[i] = u;
    }
}

// ---------------------------------------------------------------------------
// TF32 SGEMM on pre-converted tf32-bit operands.
// Round 7: 3-stage cp.async ring, ONE __syncthreads per k-iter.
// 128x128 tile, BK=32, 8 warps (2x4), 64x32 warp tile, no cvt in hot loop.
// ---------------------------------------------------------------------------
#define APITCH 36
#define BPITCH 136
#define ASTAGE (128 * APITCH)
#define BSTAGE (32 * BPITCH)

__global__ __launch_bounds__(256, 2) void sgemm_tf32(
    const unsigned* __restrict__ A, const unsigned* __restrict__ B,
    const float* __restrict__ bias, void* __restrict__ Cout,
    int M, int N, int K, int writeTf32)
{
    extern __shared__ unsigned smg[];
    unsigned* As = smg;                 // [3][128*36]
    unsigned* Bs = smg + 3 * ASTAGE;    // [3][32*136]

    const int tid = threadIdx.x;
    const int bx = blockIdx.x, by = blockIdx.y;
    const int lane = tid & 31, wid = tid >> 5;
    const int g = lane >> 2, tig = lane & 3;
    const int wm = (wid & 1) * 64;
    const int wn = (wid >> 1) * 32;

    const int ra = tid >> 1;              // A row 0..127
    const int ca = (tid & 1) * 16;        // A col half
    const int rb = tid >> 3;              // B row 0..31
    const int cb = (tid & 7) * 16;        // B col chunk

    const unsigned* aptr = A + (size_t)(by * 128 + ra) * K + ca;
    const unsigned* bptr = B + (size_t)rb * N + bx * 128 + cb;

    const unsigned sa_base = sptr(&As[ra * APITCH + ca]);
    const unsigned sb_base = sptr(&Bs[rb * BPITCH + cb]);

    float acc[4][4][4];
#pragma unroll
    for (int mt = 0; mt < 4; mt++)
#pragma unroll
        for (int nt = 0; nt < 4; nt++)
#pragma unroll
            for (int i = 0; i < 4; i++) acc[mt][nt][i] = 0.0f;

    const int nt_iters = K >> 5;

    // prologue: issue stages 0 and 1
#pragma unroll
    for (int p = 0; p < 2; p++) {
        const unsigned* ag = aptr + p * 32;
        const unsigned* bg = bptr + (size_t)p * 32 * N;
        const unsigned sa = sa_base + p * (ASTAGE * 4);
        const unsigned sb = sb_base + p * (BSTAGE * 4);
#pragma unroll
        for (int i = 0; i < 4; i++) cpa16(sa + i * 16, ag + i * 4);
#pragma unroll
        for (int i = 0; i < 4; i++) cpa16(sb + i * 16, bg + i * 4);
        asm volatile("cp.async.commit_group;\n");
    }

    for (int t = 0; t < nt_iters; t++) {
        if (t + 1 < nt_iters)
            asm volatile("cp.async.wait_group 1;\n");
        else
            asm volatile("cp.async.wait_group 0;\n");
        __syncthreads();  // stage t visible; stage (t+2)%3 buffer free (read at t-1)

        if (t + 2 < nt_iters) {
            const int s = (t + 2) % 3;
            const unsigned* ag = aptr + (t + 2) * 32;
            const unsigned* bg = bptr + (size_t)(t + 2) * 32 * N;
            const unsigned sa = sa_base + s * (ASTAGE * 4);
            const unsigned sb = sb_base + s * (BSTAGE * 4);
#pragma unroll
            for (int i = 0; i < 4; i++) cpa16(sa + i * 16, ag + i * 4);
#pragma unroll
            for (int i = 0; i < 4; i++) cpa16(sb + i * 16, bg + i * 4);
        }
        asm volatile("cp.async.commit_group;\n");

        const unsigned* Ab = As + (t % 3) * ASTAGE;
        const unsigned* Bb = Bs + (t % 3) * BSTAGE;

#pragma unroll
        for (int ks = 0; ks < 4; ks++) {
            const int k0 = ks * 8;
            unsigned af[4][4], bf[4][2];
#pragma unroll
            for (int mt = 0; mt < 4; mt++) {
                int r0 = wm + mt * 16 + g;
                af[mt][0] = Ab[r0 * APITCH + k0 + tig];
                af[mt][1] = Ab[(r0 + 8) * APITCH + k0 + tig];
                af[mt][2] = Ab[r0 * APITCH + k0 + tig + 4];
                af[mt][3] = Ab[(r0 + 8) * APITCH + k0 + tig + 4];
            }
#pragma unroll
            for (int nt = 0; nt < 4; nt++) {
                int c0 = wn + nt * 8 + g;
                bf[nt][0] = Bb[(k0 + tig) * BPITCH + c0];
                bf[nt][1] = Bb[(k0 + tig + 4) * BPITCH + c0];
            }
#pragma unroll
            for (int mt = 0; mt < 4; mt++)
#pragma unroll
                for (int nt = 0; nt < 4; nt++)
                    mma_tf32(acc[mt][nt], af[mt], bf[nt]);
        }
    }

    if (writeTf32) {
        unsigned* C = (unsigned*)Cout;
#pragma unroll
        for (int mt = 0; mt < 4; mt++) {
            int row = by * 128 + wm + mt * 16 + g;
#pragma unroll
            for (int nt = 0; nt < 4; nt++) {
                int col = bx * 128 + wn + nt * 8 + 2 * tig;
                uint2 s0, s1;
                s0.x = f2tf32(acc[mt][nt][0]); s0.y = f2tf32(acc[mt][nt][1]);
                s1.x = f2tf32(acc[mt][nt][2]); s1.y = f2tf32(acc[mt][nt][3]);
                *(uint2*)(C + (size_t)row * N + col) = s0;
                *(uint2*)(C + (size_t)(row + 8) * N + col) = s1;
            }
        }
    } else {
        float* C = (float*)Cout;
        float bv0[4], bv1[4];
#pragma unroll
        for (int nt = 0; nt < 4; nt++) {
            int col = bx * 128 + wn + nt * 8 + 2 * tig;
            bv0[nt] = bias ? bias[col] : 0.0f;
            bv1[nt] = bias ? bias[col + 1] : 0.0f;
        }
#pragma unroll
        for (int mt = 0; mt < 4; mt++) {
            int row = by * 128 + wm + mt * 16 + g;
#pragma unroll
            for (int nt = 0; nt < 4; nt++) {
                int col = bx * 128 + wn + nt * 8 + 2 * tig;
                float2 s0, s1;
                s0.x = acc[mt][nt][0] + bv0[nt];
                s0.y = acc[mt][nt][1] + bv1[nt];
                s1.x = acc[mt][nt][2] + bv0[nt];
                s1.y = acc[mt][nt][3] + bv1[nt];
                *(float2*)(C + (size_t)row * N + col) = s0;
                *(float2*)(C + (size_t)(row + 8) * N + col) = s1;
            }
        }
    }
}

// ---------------------------------------------------------------------------
// Tensor-core flash attention (round-6 body, now 2 CTAs/SM).
// qkv already tf32 bits -> no cvt on Q/K/V loads; ctx written as tf32 bits.
// ---------------------------------------------------------------------------
#define QP 68
#define VP 72

__global__ __launch_bounds__(256, 2) void attn_tc(
    const unsigned* __restrict__ qkv, const int* __restrict__ mask,
    unsigned* __restrict__ ctx)
{
    extern __shared__ unsigned sm[];
    unsigned* Qf = sm;                       // [128][68]  (aliased by Ps)
    unsigned* Kf = sm + 128 * QP;            // [64 keys][68 dims]
    unsigned* Vf = Kf + 64 * QP;             // [64 keys][72 dims]
    float*    Mk = (float*)(Vf + 64 * VP);   // [64]
    unsigned* Ps = Qf;

    const int tid = threadIdx.x;
    const int lane = tid & 31, wid = tid >> 5;
    const int g = lane >> 2, tig = lane & 3;
    const int W = wid * 16;

    const int q0 = blockIdx.x * 128;
    const int h  = blockIdx.y;
    const int b  = blockIdx.z;
    const size_t baseRow = (size_t)b * 2048;

#pragma unroll
    for (int i = 0; i < 8; i++) {
        int lin = tid + 256 * i;
        int r = lin >> 4, a4 = lin & 15;
        uint4 v = *(const uint4*)(qkv + (baseRow + q0 + r) * 3072 + h * 64 + a4 * 4);
        *(uint4*)&Qf[r * QP + a4 * 4] = v;
    }
    __syncthreads();

    unsigned qa[8][4];
#pragma unroll
    for (int ks = 0; ks < 8; ks++) {
        qa[ks][0] = Qf[(W + g) * QP + ks * 8 + tig];
        qa[ks][1] = Qf[(W + g + 8) * QP + ks * 8 + tig];
        qa[ks][2] = Qf[(W + g) * QP + ks * 8 + tig + 4];
        qa[ks][3] = Qf[(W + g + 8) * QP + ks * 8 + tig + 4];
    }
    __syncthreads();  // Q fully consumed; Ps may now overwrite Qf

    float O[8][4];
#pragma unroll
    for (int nt = 0; nt < 8; nt++)
#pragma unroll
        for (int i = 0; i < 4; i++) O[nt][i] = 0.0f;
    float mA = -1e30f, mB = -1e30f, lA = 0.0f, lB = 0.0f;

    for (int t = 0; t < 32; t++) {
        const int k0g = t * 64;
        __syncthreads();

#pragma unroll
        for (int i = 0; i < 4; i++) {
            int lin = tid + 256 * i;
            int key = lin >> 4, a4 = lin & 15;
            const unsigned* src = qkv + (baseRow + k0g + key) * 3072 + h * 64;
            uint4 kv = *(const uint4*)(src + 1024 + a4 * 4);
            *(uint4*)&Kf[key * QP + a4 * 4] = kv;
            uint4 vv = *(const uint4*)(src + 2048 + a4 * 4);
            *(uint4*)&Vf[key * VP + a4 * 4] = vv;
        }
        if (tid < 64) Mk[tid] = (float)mask[b * 2048 + k0g + tid];
        __syncthreads();

        float s[8][4];
#pragma unroll
        for (int nt = 0; nt < 8; nt++)
#pragma unroll
            for (int i = 0; i < 4; i++) s[nt][i] = 0.0f;

#pragma unroll
        for (int nt = 0; nt < 8; nt++) {
            const int key = nt * 8 + g;
#pragma unroll
            for (int ks = 0; ks < 8; ks++) {
                unsigned bf[2];
                bf[0] = Kf[key * QP + ks * 8 + tig];
                bf[1] = Kf[key * QP + ks * 8 + tig + 4];
                mma_tf32(s[nt], qa[ks], bf);
            }
        }

        float mxA = -1e30f, mxB = -1e30f;
#pragma unroll
        for (int nt = 0; nt < 8; nt++) {
            const int c = nt * 8 + 2 * tig;
            const float m0 = Mk[c], m1 = Mk[c + 1];
            s[nt][0] = (m0 == 0.0f) ? NEGV : s[nt][0] * 0.125f;
            s[nt][1] = (m1 == 0.0f) ? NEGV : s[nt][1] * 0.125f;
            s[nt][2] = (m0 == 0.0f) ? NEGV : s[nt][2] * 0.125f;
            s[nt][3] = (m1 == 0.0f) ? NEGV : s[nt][3] * 0.125f;
            mxA = fmaxf(mxA, fmaxf(s[nt][0], s[nt][1]));
            mxB = fmaxf(mxB, fmaxf(s[nt][2], s[nt][3]));
        }
        mxA = fmaxf(mxA, __shfl_xor_sync(0xffffffffu, mxA, 1));
        mxA = fmaxf(mxA, __shfl_xor_sync(0xffffffffu, mxA, 2));
        mxB = fmaxf(mxB, __shfl_xor_sync(0xffffffffu, mxB, 1));
        mxB = fmaxf(mxB, __shfl_xor_sync(0xffffffffu, mxB, 2));

        const float mnA = fmaxf(mA, mxA);
        const float mnB = fmaxf(mB, mxB);
        const float alphaA = __expf(mA - mnA);
        const float alphaB = __expf(mB - mnB);
        float sumA = 0.0f, sumB = 0.0f;
#pragma unroll
        for (int nt = 0; nt < 8; nt++) {
            s[nt][0] = __expf(s[nt][0] - mnA);
            s[nt][1] = __expf(s[nt][1] - mnA);
            s[nt][2] = __expf(s[nt][2] - mnB);
            s[nt][3] = __expf(s[nt][3] - mnB);
            sumA += s[nt][0] + s[nt][1];
            sumB += s[nt][2] + s[nt][3];
        }
        sumA += __shfl_xor_sync(0xffffffffu, sumA, 1);
        sumA += __shfl_xor_sync(0xffffffffu, sumA, 2);
        sumB += __shfl_xor_sync(0xffffffffu, sumB, 1);
        sumB += __shfl_xor_sync(0xffffffffu, sumB, 2);
        lA = lA * alphaA + sumA;  mA = mnA;
        lB = lB * alphaB + sumB;  mB = mnB;
#pragma unroll
        for (int nt = 0; nt < 8; nt++) {
            O[nt][0] *= alphaA; O[nt][1] *= alphaA;
            O[nt][2] *= alphaB; O[nt][3] *= alphaB;
        }

#pragma unroll
        for (int nt = 0; nt < 8; nt++) {
            const int c = nt * 8 + 2 * tig;
            Ps[(W + g) * QP + c]     = f2tf32(s[nt][0]);
            Ps[(W + g) * QP + c + 1] = f2tf32(s[nt][1]);
            Ps[(W + g + 8) * QP + c]     = f2tf32(s[nt][2]);
            Ps[(W + g + 8) * QP + c + 1] = f2tf32(s[nt][3]);
        }
        __syncwarp();

        unsigned pa[8][4];
#pragma unroll
        for (int ks = 0; ks < 8; ks++) {
            pa[ks][0] = Ps[(W + g) * QP + ks * 8 + tig];
            pa[ks][1] = Ps[(W + g + 8) * QP + ks * 8 + tig];
            pa[ks][2] = Ps[(W + g) * QP + ks * 8 + tig + 4];
            pa[ks][3] = Ps[(W + g + 8) * QP + ks * 8 + tig + 4];
        }

#pragma unroll
        for (int nt = 0; nt < 8; nt++) {
            const int d = nt * 8 + g;
#pragma unroll
            for (int ks = 0; ks < 8; ks++) {
                unsigned bf[2];
                bf[0] = Vf[(ks * 8 + tig) * VP + d];
                bf[1] = Vf[(ks * 8 + tig + 4) * VP + d];
                mma_tf32(O[nt], pa[ks], bf);
            }
        }
    }

    // epilogue: ctx stored as tf32 bits (gemm2 consumes them directly)
    const float invA = 1.0f / lA;
    const float invB = 1.0f / lB;
    const size_t rowA = baseRow + q0 + W + g;
#pragma unroll
    for (int nt = 0; nt < 8; nt++) {
        const int col = h * 64 + nt * 8 + 2 * tig;
        uint2 oA, oB;
        oA.x = f2tf32(O[nt][0] * invA); oA.y = f2tf32(O[nt][1] * invA);
        oB.x = f2tf32(O[nt][2] * invB); oB.y = f2tf32(O[nt][3] * invB);
        *(uint2*)(ctx + rowA * 1024 + col) = oA;
        *(uint2*)(ctx + (rowA + 8) * 1024 + col) = oB;
    }
}

// ---------------------------------------------------------------------------
extern "C" void kernel_launch(void* const* d_in, const int* in_sizes, int n_in,
                              void* d_out, int out_size)
{
    const float* qs   = (const float*)d_in[0];
    const int*   mask = (const int*)d_in[1];
    const float* Wqkv = (const float*)d_in[2];
    const float* Wout = (const float*)d_in[3];
    const float* bout = (const float*)d_in[4];
    float* out = (float*)d_out;

    unsigned *qkvP, *ctxP, *qsT, *wqkvT, *woutT;
    cudaGetSymbolAddress((void**)&qkvP,  g_qkv);
    cudaGetSymbolAddress((void**)&ctxP,  g_ctx);
    cudaGetSymbolAddress((void**)&qsT,   g_qsT);
    cudaGetSymbolAddress((void**)&wqkvT, g_wqkvT);
    cudaGetSymbolAddress((void**)&woutT, g_woutT);

    const int gemmSmem = 3 * (ASTAGE + BSTAGE) * 4;  // 107520 B
    cudaFuncSetAttribute(sgemm_tf32,
                         cudaFuncAttributeMaxDynamicSharedMemorySize, gemmSmem);

    const int attnSmem = (128 * QP + 64 * QP + 64 * VP + 64) * 4;  // 70912 B
    cudaFuncSetAttribute(attn_tc,
                         cudaFuncAttributeMaxDynamicSharedMemorySize, attnSmem);

    // 0) pre-convert inputs to tf32 bits
    cvt_tf32_kernel<<<(4096 * 1024 / 4 + 255) / 256, 256>>>(
        (const float4*)qs, (uint4*)qsT, 4096 * 1024 / 4);
    cvt_tf32_kernel<<<(1024 * 3072 / 4 + 255) / 256, 256>>>(
        (const float4*)Wqkv, (uint4*)wqkvT, 1024 * 3072 / 4);
    cvt_tf32_kernel<<<(1024 * 1024 / 4 + 255) / 256, 256>>>(
        (const float4*)Wout, (uint4*)woutT, 1024 * 1024 / 4);

    // 1) qkv(tf32 bits) = qs @ Wqkv
    sgemm_tf32<<<dim3(24, 32), 256, gemmSmem>>>(
        qsT, wqkvT, nullptr, qkvP, 4096, 3072, 1024, 1);

    // 2) fused masked attention -> ctx (tf32 bits)
    attn_tc<<<dim3(16, 16, 2), 256, attnSmem>>>(qkvP, mask, ctxP);

    // 3) out = ctx @ Wout + bout  (fp32 final)
    sgemm_tf32<<<dim3(8, 32), 256, gemmSmem>>>(
        ctxP, woutT, bout, out, 4096, 1024, 1024, 0);
}

// round 8
// speedup vs baseline: 1.2539x; 1.1082x over previous
#include <cuda_runtime.h>

#define NEGV (-1000000000.0f)

// B=2 S=2048 D=1024 H=16 A=64
__device__ unsigned g_qkv[(size_t)4096 * 3072];   // row-major tf32 bits (attention input)
__device__ unsigned g_ctx[(size_t)4096 * 1024];   // A-frag layout tf32 bits (gemm2 A)
__device__ unsigned g_qsT[(size_t)4096 * 1024];   // A-frag layout (gemm1 A)
__device__ unsigned g_wqkvT[(size_t)1024 * 3072]; // B-frag layout (gemm1 B)
__device__ unsigned g_woutT[(size_t)1024 * 1024]; // B-frag layout (gemm2 B)

__device__ __forceinline__ unsigned f2tf32(float x) {
    unsigned y;
    asm("cvt.rna.tf32.f32 %0, %1;" : "=r"(y) : "f"(x));
    return y;
}

__device__ __forceinline__ void mma_tf32(float* d, const unsigned* a, const unsigned* b) {
    asm volatile(
        "mma.sync.aligned.m16n8k8.row.col.f32.tf32.tf32.f32 "
        "{%0,%1,%2,%3}, {%4,%5,%6,%7}, {%8,%9}, {%0,%1,%2,%3};"
        : "+f"(d[0]), "+f"(d[1]), "+f"(d[2]), "+f"(d[3])
        : "r"(a[0]), "r"(a[1]), "r"(a[2]), "r"(a[3]), "r"(b[0]), "r"(b[1]));
}

__device__ __forceinline__ unsigned sptr(const void* p) {
    return (unsigned)__cvta_generic_to_shared(p);
}

__device__ __forceinline__ void cpa16(unsigned s, const void* g) {
    asm volatile("cp.async.cg.shared.global [%0], [%1], 16;\n" :: "r"(s), "l"(g));
}

// ---------------------------------------------------------------------------
// Permute fp32 [R,C] row-major -> A-fragment tile layout (tf32 bits).
// Tile 16(m)x8(k) = 128 words, tiles mt-major: ((mt*Ct)+kt)*128.
// Word within tile: (g*4+tig)*4 + ik*2 + im,  where m=g+im*8, k=tig+ik*4.
// ---------------------------------------------------------------------------
__global__ __launch_bounds__(256) void permA_tf32(
    const float4* __restrict__ src, unsigned* __restrict__ dst,
    int C, int total4)
{
    int idx = blockIdx.x * 256 + threadIdx.x;
    if (idx >= total4) return;
    const int C4 = C >> 2;
    const int r = idx / C4;
    const int k = (idx - r * C4) * 4;
    float4 v = src[idx];
    const int Ct = C >> 3;
    const int mt = r >> 4, rm = r & 15;
    const int gp = rm & 7, im = rm >> 3;
    const int kt = k >> 3, ik = (k & 7) >> 2;
    unsigned* tb = dst + ((size_t)mt * Ct + kt) * 128 + ik * 2 + im;
    tb[(gp * 4 + 0) * 4] = f2tf32(v.x);
    tb[(gp * 4 + 1) * 4] = f2tf32(v.y);
    tb[(gp * 4 + 2) * 4] = f2tf32(v.z);
    tb[(gp * 4 + 3) * 4] = f2tf32(v.w);
}

// ---------------------------------------------------------------------------
// Permute fp32 [K,N] row-major -> B-fragment tile layout (tf32 bits).
// Tile 8(k)x8(n) = 64 words, tiles kt-major: ((kt*Nt)+nt)*64.
// Word within tile: (g*4+tig)*2 + ik, where n=g, k=tig+ik*4.
// ---------------------------------------------------------------------------
__global__ __launch_bounds__(256) void permB_tf32(
    const float4* __restrict__ src, unsigned* __restrict__ dst,
    int N, int total4)
{
    int idx = blockIdx.x * 256 + threadIdx.x;
    if (idx >= total4) return;
    const int N4 = N >> 2;
    const int k = idx / N4;
    const int n = (idx - k * N4) * 4;
    float4 v = src[idx];
    const int Nt = N >> 3;
    const int kt = k >> 3, tg = k & 3, ik = (k & 7) >> 2;
    const int nt = n >> 3, g0 = n & 7;   // g0 in {0,4}
    unsigned* tb = dst + ((size_t)kt * Nt + nt) * 64 + tg * 2 + ik;
    tb[(g0 + 0) * 8] = f2tf32(v.x);
    tb[(g0 + 1) * 8] = f2tf32(v.y);
    tb[(g0 + 2) * 8] = f2tf32(v.z);
    tb[(g0 + 3) * 8] = f2tf32(v.w);
}

// ---------------------------------------------------------------------------
// TF32 SGEMM on fragment-major operands.
// 128x128 tile, BK=32, 256 threads (8 warps 2x4), warp tile 64x32.
// Stage = 8 A-tiles*512w + 4 k-rows*1024w = 4096+4096 words (16KB+16KB).
// Fragment loads: LDS.128 (A) / LDS.64 (B), linear, conflict-free.
// 3-stage cp.async ring, one __syncthreads per k-iter.
// ---------------------------------------------------------------------------
#define STG_W 4096

__global__ __launch_bounds__(256, 2) void sgemm_tf32(
    const unsigned* __restrict__ A, const unsigned* __restrict__ B,
    const float* __restrict__ bias, void* __restrict__ Cout,
    int M, int N, int K, int writeTf32)
{
    extern __shared__ unsigned smg[];
    unsigned* As = smg;                 // [3][4096]
    unsigned* Bs = smg + 3 * STG_W;     // [3][4096]

    const int tid = threadIdx.x;
    const int bx = blockIdx.x, by = blockIdx.y;
    const int lane = tid & 31, wid = tid >> 5;
    const int g = lane >> 2, tig = lane & 3;
    const int wm = (wid & 1) * 64;
    const int wn = (wid >> 1) * 32;
    const int Ct = K >> 3;              // A k-tiles
    const int Nt = N >> 3;              // B n-tiles

    // loader mapping
    const int amt = tid >> 5;           // A m-tile 0..7
    const int aq  = (tid & 31) * 16;    // word offset in 512-word chunk
    const int bkt = tid >> 6;           // B k-tile 0..3
    const int bq  = (tid & 63) * 16;    // word offset in 1024-word chunk

    const unsigned* abase = A + ((size_t)(by * 8 + amt) * Ct) * 128 + aq;
    const unsigned* bbase = B + (size_t)bx * 16 * 64 + bq;

    const unsigned sa_base = sptr(&As[amt * 512 + aq]);
    const unsigned sb_base = sptr(&Bs[bkt * 1024 + bq]);

    float acc[4][4][4];
#pragma unroll
    for (int mt = 0; mt < 4; mt++)
#pragma unroll
        for (int nt = 0; nt < 4; nt++)
#pragma unroll
            for (int i = 0; i < 4; i++) acc[mt][nt][i] = 0.0f;

    const int nt_iters = K >> 5;

    // prologue: issue stages 0 and 1
#pragma unroll
    for (int p = 0; p < 2; p++) {
        const unsigned* ag = abase + p * 4 * 128;
        const unsigned* bg = bbase + (size_t)(p * 4 + bkt) * Nt * 64;
        const unsigned sa = sa_base + p * (STG_W * 4);
        const unsigned sb = sb_base + p * (STG_W * 4);
#pragma unroll
        for (int i = 0; i < 4; i++) cpa16(sa + i * 16, ag + i * 4);
#pragma unroll
        for (int i = 0; i < 4; i++) cpa16(sb + i * 16, bg + i * 4);
        asm volatile("cp.async.commit_group;\n");
    }

    for (int t = 0; t < nt_iters; t++) {
        if (t + 1 < nt_iters)
            asm volatile("cp.async.wait_group 1;\n");
        else
            asm volatile("cp.async.wait_group 0;\n");
        __syncthreads();

        if (t + 2 < nt_iters) {
            const int s = (t + 2) % 3;
            const unsigned* ag = abase + (t + 2) * 4 * 128;
            const unsigned* bg = bbase + (size_t)((t + 2) * 4 + bkt) * Nt * 64;
            const unsigned sa = sa_base + s * (STG_W * 4);
            const unsigned sb = sb_base + s * (STG_W * 4);
#pragma unroll
            for (int i = 0; i < 4; i++) cpa16(sa + i * 16, ag + i * 4);
#pragma unroll
            for (int i = 0; i < 4; i++) cpa16(sb + i * 16, bg + i * 4);
        }
        asm volatile("cp.async.commit_group;\n");

        const unsigned* Ab = As + (t % 3) * STG_W;
        const unsigned* Bb = Bs + (t % 3) * STG_W;

#pragma unroll
        for (int ks = 0; ks < 4; ks++) {
            uint4 af[4];
            uint2 bf[4];
#pragma unroll
            for (int mt = 0; mt < 4; mt++)
                af[mt] = *(const uint4*)&Ab[(((wid & 1) * 4 + mt) * 4 + ks) * 128 + lane * 4];
#pragma unroll
            for (int nt = 0; nt < 4; nt++)
                bf[nt] = *(const uint2*)&Bb[(ks * 16 + (wid >> 1) * 4 + nt) * 64 + lane * 2];
#pragma unroll
            for (int mt = 0; mt < 4; mt++)
#pragma unroll
                for (int nt = 0; nt < 4; nt++)
                    mma_tf32(acc[mt][nt], (const unsigned*)&af[mt], (const unsigned*)&bf[nt]);
        }
    }

    if (writeTf32) {
        // row-major tf32 bits (attention consumes qkv row-major)
        unsigned* C = (unsigned*)Cout;
#pragma unroll
        for (int mt = 0; mt < 4; mt++) {
            int row = by * 128 + wm + mt * 16 + g;
#pragma unroll
            for (int nt = 0; nt < 4; nt++) {
                int col = bx * 128 + wn + nt * 8 + 2 * tig;
                uint2 s0, s1;
                s0.x = f2tf32(acc[mt][nt][0]); s0.y = f2tf32(acc[mt][nt][1]);
                s1.x = f2tf32(acc[mt][nt][2]); s1.y = f2tf32(acc[mt][nt][3]);
                *(uint2*)(C + (size_t)row * N + col) = s0;
                *(uint2*)(C + (size_t)(row + 8) * N + col) = s1;
            }
        }
    } else {
        float* C = (float*)Cout;
        float bv0[4], bv1[4];
#pragma unroll
        for (int nt = 0; nt < 4; nt++) {
            int col = bx * 128 + wn + nt * 8 + 2 * tig;
            bv0[nt] = bias ? bias[col] : 0.0f;
            bv1[nt] = bias ? bias[col + 1] : 0.0f;
        }
#pragma unroll
        for (int mt = 0; mt < 4; mt++) {
            int row = by * 128 + wm + mt * 16 + g;
#pragma unroll
            for (int nt = 0; nt < 4; nt++) {
                int col = bx * 128 + wn + nt * 8 + 2 * tig;
                float2 s0, s1;
                s0.x = acc[mt][nt][0] + bv0[nt];
                s0.y = acc[mt][nt][1] + bv1[nt];
                s1.x = acc[mt][nt][2] + bv0[nt];
                s1.y = acc[mt][nt][3] + bv1[nt];
                *(float2*)(C + (size_t)row * N + col) = s0;
                *(float2*)(C + (size_t)(row + 8) * N + col) = s1;
            }
        }
    }
}

// ---------------------------------------------------------------------------
// Tensor-core flash attention (round-7 body). Epilogue now writes ctx in the
// A-fragment tile layout consumed by gemm2 (pure index permutation).
// ---------------------------------------------------------------------------
#define QP 68
#define VP 72

__global__ __launch_bounds__(256, 2) void attn_tc(
    const unsigned* __restrict__ qkv, const int* __restrict__ mask,
    unsigned* __restrict__ ctx)
{
    extern __shared__ unsigned sm[];
    unsigned* Qf = sm;                       // [128][68]  (aliased by Ps)
    unsigned* Kf = sm + 128 * QP;            // [64 keys][68 dims]
    unsigned* Vf = Kf + 64 * QP;             // [64 keys][72 dims]
    float*    Mk = (float*)(Vf + 64 * VP);   // [64]
    unsigned* Ps = Qf;

    const int tid = threadIdx.x;
    const int lane = tid & 31, wid = tid >> 5;
    const int g = lane >> 2, tig = lane & 3;
    const int W = wid * 16;

    const int q0 = blockIdx.x * 128;
    const int h  = blockIdx.y;
    const int b  = blockIdx.z;
    const size_t baseRow = (size_t)b * 2048;

#pragma unroll
    for (int i = 0; i < 8; i++) {
        int lin = tid + 256 * i;
        int r = lin >> 4, a4 = lin & 15;
        uint4 v = *(const uint4*)(qkv + (baseRow + q0 + r) * 3072 + h * 64 + a4 * 4);
        *(uint4*)&Qf[r * QP + a4 * 4] = v;
    }
    __syncthreads();

    unsigned qa[8][4];
#pragma unroll
    for (int ks = 0; ks < 8; ks++) {
        qa[ks][0] = Qf[(W + g) * QP + ks * 8 + tig];
        qa[ks][1] = Qf[(W + g + 8) * QP + ks * 8 + tig];
        qa[ks][2] = Qf[(W + g) * QP + ks * 8 + tig + 4];
        qa[ks][3] = Qf[(W + g + 8) * QP + ks * 8 + tig + 4];
    }
    __syncthreads();  // Q fully consumed; Ps may now overwrite Qf

    float O[8][4];
#pragma unroll
    for (int nt = 0; nt < 8; nt++)
#pragma unroll
        for (int i = 0; i < 4; i++) O[nt][i] = 0.0f;
    float mA = -1e30f, mB = -1e30f, lA = 0.0f, lB = 0.0f;

    for (int t = 0; t < 32; t++) {
        const int k0g = t * 64;
        __syncthreads();

#pragma unroll
        for (int i = 0; i < 4; i++) {
            int lin = tid + 256 * i;
            int key = lin >> 4, a4 = lin & 15;
            const unsigned* src = qkv + (baseRow + k0g + key) * 3072 + h * 64;
            uint4 kv = *(const uint4*)(src + 1024 + a4 * 4);
            *(uint4*)&Kf[key * QP + a4 * 4] = kv;
            uint4 vv = *(const uint4*)(src + 2048 + a4 * 4);
            *(uint4*)&Vf[key * VP + a4 * 4] = vv;
        }
        if (tid < 64) Mk[tid] = (float)mask[b * 2048 + k0g + tid];
        __syncthreads();

        float s[8][4];
#pragma unroll
        for (int nt = 0; nt < 8; nt++)
#pragma unroll
            for (int i = 0; i < 4; i++) s[nt][i] = 0.0f;

#pragma unroll
        for (int nt = 0; nt < 8; nt++) {
            const int key = nt * 8 + g;
#pragma unroll
            for (int ks = 0; ks < 8; ks++) {
                unsigned bf[2];
                bf[0] = Kf[key * QP + ks * 8 + tig];
                bf[1] = Kf[key * QP + ks * 8 + tig + 4];
                mma_tf32(s[nt], qa[ks], bf);
            }
        }

        float mxA = -1e30f, mxB = -1e30f;
#pragma unroll
        for (int nt = 0; nt < 8; nt++) {
            const int c = nt * 8 + 2 * tig;
            const float m0 = Mk[c], m1 = Mk[c + 1];
            s[nt][0] = (m0 == 0.0f) ? NEGV : s[nt][0] * 0.125f;
            s[nt][1] = (m1 == 0.0f) ? NEGV : s[nt][1] * 0.125f;
            s[nt][2] = (m0 == 0.0f) ? NEGV : s[nt][2] * 0.125f;
            s[nt][3] = (m1 == 0.0f) ? NEGV : s[nt][3] * 0.125f;
            mxA = fmaxf(mxA, fmaxf(s[nt][0], s[nt][1]));
            mxB = fmaxf(mxB, fmaxf(s[nt][2], s[nt][3]));
        }
        mxA = fmaxf(mxA, __shfl_xor_sync(0xffffffffu, mxA, 1));
        mxA = fmaxf(mxA, __shfl_xor_sync(0xffffffffu, mxA, 2));
        mxB = fmaxf(mxB, __shfl_xor_sync(0xffffffffu, mxB, 1));
        mxB = fmaxf(mxB, __shfl_xor_sync(0xffffffffu, mxB, 2));

        const float mnA = fmaxf(mA, mxA);
        const float mnB = fmaxf(mB, mxB);
        const float alphaA = __expf(mA - mnA);
        const float alphaB = __expf(mB - mnB);
        float sumA = 0.0f, sumB = 0.0f;
#pragma unroll
        for (int nt = 0; nt < 8; nt++) {
            s[nt][0] = __expf(s[nt][0] - mnA);
            s[nt][1] = __expf(s[nt][1] - mnA);
            s[nt][2] = __expf(s[nt][2] - mnB);
            s[nt][3] = __expf(s[nt][3] - mnB);
            sumA += s[nt][0] + s[nt][1];
            sumB += s[nt][2] + s[nt][3];
        }
        sumA += __shfl_xor_sync(0xffffffffu, sumA, 1);
        sumA += __shfl_xor_sync(0xffffffffu, sumA, 2);
        sumB += __shfl_xor_sync(0xffffffffu, sumB, 1);
        sumB += __shfl_xor_sync(0xffffffffu, sumB, 2);
        lA = lA * alphaA + sumA;  mA = mnA;
        lB = lB * alphaB + sumB;  mB = mnB;
#pragma unroll
        for (int nt = 0; nt < 8; nt++) {
            O[nt][0] *= alphaA; O[nt][1] *= alphaA;
            O[nt][2] *= alphaB; O[nt][3] *= alphaB;
        }

#pragma unroll
        for (int nt = 0; nt < 8; nt++) {
            const int c = nt * 8 + 2 * tig;
            Ps[(W + g) * QP + c]     = f2tf32(s[nt][0]);
            Ps[(W + g) * QP + c + 1] = f2tf32(s[nt][1]);
            Ps[(W + g + 8) * QP + c]     = f2tf32(s[nt][2]);
            Ps[(W + g + 8) * QP + c + 1] = f2tf32(s[nt][3]);
        }
        __syncwarp();

        unsigned pa[8][4];
#pragma unroll
        for (int ks = 0; ks < 8; ks++) {
            pa[ks][0] = Ps[(W + g) * QP + ks * 8 + tig];
            pa[ks][1] = Ps[(W + g + 8) * QP + ks * 8 + tig];
            pa[ks][2] = Ps[(W + g) * QP + ks * 8 + tig + 4];
            pa[ks][3] = Ps[(W + g + 8) * QP + ks * 8 + tig + 4];
        }

#pragma unroll
        for (int nt = 0; nt < 8; nt++) {
            const int d = nt * 8 + g;
#pragma unroll
            for (int ks = 0; ks < 8; ks++) {
                unsigned bf[2];
                bf[0] = Vf[(ks * 8 + tig) * VP + d];
                bf[1] = Vf[(ks * 8 + tig + 4) * VP + d];
                mma_tf32(O[nt], pa[ks], bf);
            }
        }
    }

    // epilogue: ctx in A-frag tile layout (Ct = 1024/8 = 128)
    // rows: R0 = baseRow+q0+W+g (im=0), R0+8 (im=1); mt = (baseRow+q0+W)/16
    const float invA = 1.0f / lA;
    const float invB = 1.0f / lB;
    const int mt = (int)((baseRow + q0 + W) >> 4);
#pragma unroll
    for (int nt = 0; nt < 8; nt++) {
        const int kt = h * 8 + nt;
        unsigned* tb = ctx + ((size_t)mt * 128 + kt) * 128;
        const int tig2 = 2 * tig;
        const int ik = tig2 >> 2, tp = tig2 & 3;
        uint2 w0, w1;
        w0.x = f2tf32(O[nt][0] * invA);  // (R0,   c)
        w0.y = f2tf32(O[nt][2] * invB);  // (R0+8, c)
        w1.x = f2tf32(O[nt][1] * invA);  // (R0,   c+1)
        w1.y = f2tf32(O[nt][3] * invB);  // (R0+8, c+1)
        *(uint2*)&tb[(g * 4 + tp) * 4 + ik * 2]     = w0;
        *(uint2*)&tb[(g * 4 + tp + 1) * 4 + ik * 2] = w1;
    }
}

// ---------------------------------------------------------------------------
extern "C" void kernel_launch(void* const* d_in, const int* in_sizes, int n_in,
                              void* d_out, int out_size)
{
    const float* qs   = (const float*)d_in[0];
    const int*   mask = (const int*)d_in[1];
    const float* Wqkv = (const float*)d_in[2];
    const float* Wout = (const float*)d_in[3];
    const float* bout = (const float*)d_in[4];
    float* out = (float*)d_out;

    unsigned *qkvP, *ctxP, *qsT, *wqkvT, *woutT;
    cudaGetSymbolAddress((void**)&qkvP,  g_qkv);
    cudaGetSymbolAddress((void**)&ctxP,  g_ctx);
    cudaGetSymbolAddress((void**)&qsT,   g_qsT);
    cudaGetSymbolAddress((void**)&wqkvT, g_wqkvT);
    cudaGetSymbolAddress((void**)&woutT, g_woutT);

    const int gemmSmem = 6 * STG_W * 4;  // 98304 B
    cudaFuncSetAttribute(sgemm_tf32,
                         cudaFuncAttributeMaxDynamicSharedMemorySize, gemmSmem);

    const int attnSmem = (128 * QP + 64 * QP + 64 * VP + 64) * 4;  // 70912 B
    cudaFuncSetAttribute(attn_tc,
                         cudaFuncAttributeMaxDynamicSharedMemorySize, attnSmem);

    // 0) pre-convert + permute inputs into fragment-major tf32 layouts
    permA_tf32<<<4096, 256>>>((const float4*)qs, qsT, 1024, 4096 * 1024 / 4);
    permB_tf32<<<3072, 256>>>((const float4*)Wqkv, wqkvT, 3072, 1024 * 3072 / 4);
    permB_tf32<<<1024, 256>>>((const float4*)Wout, woutT, 1024, 1024 * 1024 / 4);

    // 1) qkv(tf32, row-major) = qs @ Wqkv
    sgemm_tf32<<<dim3(24, 32), 256, gemmSmem>>>(
        qsT, wqkvT, nullptr, qkvP, 4096, 3072, 1024, 1);

    // 2) fused masked attention -> ctx (A-frag layout)
    attn_tc<<<dim3(16, 16, 2), 256, attnSmem>>>(qkvP, mask, ctxP);

    // 3) out = ctx @ Wout + bout  (fp32 final)
    sgemm_tf32<<<dim3(8, 32), 256, gemmSmem>>>(
        ctxP, woutT, bout, out, 4096, 1024, 1024, 0);
}

// round 9
// speedup vs baseline: 1.3178x; 1.0510x over previous
#include <cuda_runtime.h>

#define NEGV (-1000000000.0f)

// B=2 S=2048 D=1024 H=16 A=64
// Fragment-major tf32-bit buffers:
__device__ unsigned g_q[(size_t)4096 * 1024];     // A-frag per (b,h,qt,mt,kt)
__device__ unsigned g_k[(size_t)4096 * 1024];     // B-frag (n=key,k=dim) per (b,h,t)
__device__ unsigned g_v[(size_t)4096 * 1024];     // B-frag (n=dim,k=key) per (b,h,t)
__device__ unsigned g_ctx[(size_t)4096 * 1024];   // A-frag (gemm2 A)
__device__ unsigned g_qsT[(size_t)4096 * 1024];   // A-frag (gemm1 A)
__device__ unsigned g_wqkvT[(size_t)1024 * 3072]; // B-frag (gemm1 B)
__device__ unsigned g_woutT[(size_t)1024 * 1024]; // B-frag (gemm2 B)

__device__ __forceinline__ unsigned f2tf32(float x) {
    unsigned y;
    asm("cvt.rna.tf32.f32 %0, %1;" : "=r"(y) : "f"(x));
    return y;
}

__device__ __forceinline__ void mma_tf32(float* d, const unsigned* a, const unsigned* b) {
    asm volatile(
        "mma.sync.aligned.m16n8k8.row.col.f32.tf32.tf32.f32 "
        "{%0,%1,%2,%3}, {%4,%5,%6,%7}, {%8,%9}, {%0,%1,%2,%3};"
        : "+f"(d[0]), "+f"(d[1]), "+f"(d[2]), "+f"(d[3])
        : "r"(a[0]), "r"(a[1]), "r"(a[2]), "r"(a[3]), "r"(b[0]), "r"(b[1]));
}

__device__ __forceinline__ unsigned sptr(const void* p) {
    return (unsigned)__cvta_generic_to_shared(p);
}

__device__ __forceinline__ void cpa16(unsigned s, const void* g) {
    asm volatile("cp.async.cg.shared.global [%0], [%1], 16;\n" :: "r"(s), "l"(g));
}

// ---------------------------------------------------------------------------
// Input permutation kernels (round-8 proven)
// ---------------------------------------------------------------------------
__global__ __launch_bounds__(256) void permA_tf32(
    const float4* __restrict__ src, unsigned* __restrict__ dst,
    int C, int total4)
{
    int idx = blockIdx.x * 256 + threadIdx.x;
    if (idx >= total4) return;
    const int C4 = C >> 2;
    const int r = idx / C4;
    const int k = (idx - r * C4) * 4;
    float4 v = src[idx];
    const int Ct = C >> 3;
    const int mt = r >> 4, rm = r & 15;
    const int gp = rm & 7, im = rm >> 3;
    const int kt = k >> 3, ik = (k & 7) >> 2;
    unsigned* tb = dst + ((size_t)mt * Ct + kt) * 128 + ik * 2 + im;
    tb[(gp * 4 + 0) * 4] = f2tf32(v.x);
    tb[(gp * 4 + 1) * 4] = f2tf32(v.y);
    tb[(gp * 4 + 2) * 4] = f2tf32(v.z);
    tb[(gp * 4 + 3) * 4] = f2tf32(v.w);
}

__global__ __launch_bounds__(256) void permB_tf32(
    const float4* __restrict__ src, unsigned* __restrict__ dst,
    int N, int total4)
{
    int idx = blockIdx.x * 256 + threadIdx.x;
    if (idx >= total4) return;
    const int N4 = N >> 2;
    const int k = idx / N4;
    const int n = (idx - k * N4) * 4;
    float4 v = src[idx];
    const int Nt = N >> 3;
    const int kt = k >> 3, tg = k & 3, ik = (k & 7) >> 2;
    const int nt = n >> 3, g0 = n & 7;
    unsigned* tb = dst + ((size_t)kt * Nt + nt) * 64 + tg * 2 + ik;
    tb[(g0 + 0) * 8] = f2tf32(v.x);
    tb[(g0 + 1) * 8] = f2tf32(v.y);
    tb[(g0 + 2) * 8] = f2tf32(v.z);
    tb[(g0 + 3) * 8] = f2tf32(v.w);
}

// ---------------------------------------------------------------------------
// TF32 SGEMM on fragment-major operands (round-8 proven mainloop).
// mode 0: fp32 C + bias (gemm2).  mode 1: scatter qkv into g_q/g_k/g_v
// fragment-major buffers (gemm1, M=4096, N=3072 hardcoded semantics).
// ---------------------------------------------------------------------------
#define STG_W 4096

__global__ __launch_bounds__(256, 2) void sgemm_tf32(
    const unsigned* __restrict__ A, const unsigned* __restrict__ B,
    const float* __restrict__ bias, void* __restrict__ Cout,
    unsigned* __restrict__ qbuf, unsigned* __restrict__ kbuf,
    unsigned* __restrict__ vbuf,
    int M, int N, int K, int mode)
{
    extern __shared__ unsigned smg[];
    unsigned* As = smg;                 // [3][4096]
    unsigned* Bs = smg + 3 * STG_W;     // [3][4096]

    const int tid = threadIdx.x;
    const int bx = blockIdx.x, by = blockIdx.y;
    const int lane = tid & 31, wid = tid >> 5;
    const int g = lane >> 2, tig = lane & 3;
    const int wm = (wid & 1) * 64;
    const int wn = (wid >> 1) * 32;
    const int Ct = K >> 3;
    const int Nt = N >> 3;

    const int amt = tid >> 5;
    const int aq  = (tid & 31) * 16;
    const int bkt = tid >> 6;
    const int bq  = (tid & 63) * 16;

    const unsigned* abase = A + ((size_t)(by * 8 + amt) * Ct) * 128 + aq;
    const unsigned* bbase = B + (size_t)bx * 16 * 64 + bq;

    const unsigned sa_base = sptr(&As[amt * 512 + aq]);
    const unsigned sb_base = sptr(&Bs[bkt * 1024 + bq]);

    float acc[4][4][4];
#pragma unroll
    for (int mt = 0; mt < 4; mt++)
#pragma unroll
        for (int nt = 0; nt < 4; nt++)
#pragma unroll
            for (int i = 0; i < 4; i++) acc[mt][nt][i] = 0.0f;

    const int nt_iters = K >> 5;

#pragma unroll
    for (int p = 0; p < 2; p++) {
        const unsigned* ag = abase + p * 4 * 128;
        const unsigned* bg = bbase + (size_t)(p * 4 + bkt) * Nt * 64;
        const unsigned sa = sa_base + p * (STG_W * 4);
        const unsigned sb = sb_base + p * (STG_W * 4);
#pragma unroll
        for (int i = 0; i < 4; i++) cpa16(sa + i * 16, ag + i * 4);
#pragma unroll
        for (int i = 0; i < 4; i++) cpa16(sb + i * 16, bg + i * 4);
        asm volatile("cp.async.commit_group;\n");
    }

    for (int t = 0; t < nt_iters; t++) {
        if (t + 1 < nt_iters)
            asm volatile("cp.async.wait_group 1;\n");
        else
            asm volatile("cp.async.wait_group 0;\n");
        __syncthreads();

        if (t + 2 < nt_iters) {
            const int s = (t + 2) % 3;
            const unsigned* ag = abase + (t + 2) * 4 * 128;
            const unsigned* bg = bbase + (size_t)((t + 2) * 4 + bkt) * Nt * 64;
            const unsigned sa = sa_base + s * (STG_W * 4);
            const unsigned sb = sb_base + s * (STG_W * 4);
#pragma unroll
            for (int i = 0; i < 4; i++) cpa16(sa + i * 16, ag + i * 4);
#pragma unroll
            for (int i = 0; i < 4; i++) cpa16(sb + i * 16, bg + i * 4);
        }
        asm volatile("cp.async.commit_group;\n");

        const unsigned* Ab = As + (t % 3) * STG_W;
        const unsigned* Bb = Bs + (t % 3) * STG_W;

#pragma unroll
        for (int ks = 0; ks < 4; ks++) {
            uint4 af[4];
            uint2 bf[4];
#pragma unroll
            for (int mt = 0; mt < 4; mt++)
                af[mt] = *(const uint4*)&Ab[(((wid & 1) * 4 + mt) * 4 + ks) * 128 + lane * 4];
#pragma unroll
            for (int nt = 0; nt < 4; nt++)
                bf[nt] = *(const uint2*)&Bb[(ks * 16 + (wid >> 1) * 4 + nt) * 64 + lane * 2];
#pragma unroll
            for (int mt = 0; mt < 4; mt++)
#pragma unroll
                for (int nt = 0; nt < 4; nt++)
                    mma_tf32(acc[mt][nt], (const unsigned*)&af[mt], (const unsigned*)&bf[nt]);
        }
    }

    if (mode == 1) {
        // scatter into fragment-major Q/K/V buffers
#pragma unroll
        for (int mt = 0; mt < 4; mt++) {
            const int row = by * 128 + wm + mt * 16 + g;
            const int bb = row >> 11;
            const int s = row & 2047;
#pragma unroll
            for (int nt = 0; nt < 4; nt++) {
                const int col = bx * 128 + wn + nt * 8 + 2 * tig;
                unsigned v00 = f2tf32(acc[mt][nt][0]);
                unsigned v01 = f2tf32(acc[mt][nt][1]);
                unsigned v10 = f2tf32(acc[mt][nt][2]);
                unsigned v11 = f2tf32(acc[mt][nt][3]);
                if (col < 1024) {            // Q -> A-frag per (bh, qt, mtl, kt)
                    const int h = col >> 6, d = col & 63;
                    const int bh = bb * 16 + h;
                    size_t base = (((size_t)(bh * 16 + (s >> 7)) * 8 + ((s & 127) >> 4)) * 8
                                   + (d >> 3)) * 128;
                    const int gq = s & 7;
                    const int w0 = (gq * 4 + (d & 3)) * 4 + ((d & 7) >> 2) * 2;
                    const int d1 = d + 1;
                    const int w1 = (gq * 4 + (d1 & 3)) * 4 + ((d1 & 7) >> 2) * 2;
                    uint2 u0; u0.x = v00; u0.y = v10;
                    uint2 u1; u1.x = v01; u1.y = v11;
                    *(uint2*)&qbuf[base + w0] = u0;
                    *(uint2*)&qbuf[base + w1] = u1;
                } else if (col < 2048) {     // K -> B-frag (n=key, k=dim)
                    const int h = (col - 1024) >> 6, d = (col - 1024) & 63;
                    const int bh = bb * 16 + h;
                    const int tt = s >> 6, key = s & 63;
                    unsigned* blk = kbuf + ((size_t)(bh * 32 + tt)) * 4096;
                    const int gk = key & 7;
                    const int tile0 = (d >> 3) * 8 + (key >> 3);
                    const int tile1 = (d >> 3) * 8 + ((key + 8) >> 3);
                    const int wd0 = (gk * 4 + (d & 3)) * 2 + ((d & 7) >> 2);
                    const int d1 = d + 1;
                    const int wd1 = (gk * 4 + (d1 & 3)) * 2 + ((d1 & 7) >> 2);
                    blk[tile0 * 64 + wd0] = v00;
                    blk[tile0 * 64 + wd1] = v01;
                    blk[tile1 * 64 + wd0] = v10;
                    blk[tile1 * 64 + wd1] = v11;
                } else {                     // V -> B-frag (n=dim, k=key)
                    const int h = (col - 2048) >> 6, d = (col - 2048) & 63;
                    const int bh = bb * 16 + h;
                    const int tt = s >> 6, key = s & 63;
                    unsigned* blk = vbuf + ((size_t)(bh * 32 + tt)) * 4096;
                    const int tigv = key & 3, ikv = (key & 7) >> 2;
                    const int tile0 = (key >> 3) * 8 + (d >> 3);
                    const int tile1 = ((key + 8) >> 3) * 8 + (d >> 3);
                    const int wv0 = ((d & 7) * 4 + tigv) * 2 + ikv;
                    const int d1 = d + 1;
                    const int wv1 = (((d1) & 7) * 4 + tigv) * 2 + ikv;
                    blk[tile0 * 64 + wv0] = v00;
                    blk[tile0 * 64 + wv1] = v01;
                    blk[tile1 * 64 + wv0] = v10;
                    blk[tile1 * 64 + wv1] = v11;
                }
            }
        }
    } else {
        float* C = (float*)Cout;
        float bv0[4], bv1[4];
#pragma unroll
        for (int nt = 0; nt < 4; nt++) {
            int col = bx * 128 + wn + nt * 8 + 2 * tig;
            bv0[nt] = bias ? bias[col] : 0.0f;
            bv1[nt] = bias ? bias[col + 1] : 0.0f;
        }
#pragma unroll
        for (int mt = 0; mt < 4; mt++) {
            int row = by * 128 + wm + mt * 16 + g;
#pragma unroll
            for (int nt = 0; nt < 4; nt++) {
                int col = bx * 128 + wn + nt * 8 + 2 * tig;
                float2 s0, s1;
                s0.x = acc[mt][nt][0] + bv0[nt];
                s0.y = acc[mt][nt][1] + bv1[nt];
                s1.x = acc[mt][nt][2] + bv0[nt];
                s1.y = acc[mt][nt][3] + bv1[nt];
                *(float2*)(C + (size_t)row * N + col) = s0;
                *(float2*)(C + (size_t)(row + 8) * N + col) = s1;
            }
        }
    }
}

// ---------------------------------------------------------------------------
// Fragment-major tensor-core flash attention.
// Q fragments straight from gmem (LDG.128). K/V: cp.async verbatim B-frag
// blocks, double buffered, one barrier/tile. P via per-warp A-frag smem.
// ---------------------------------------------------------------------------
#define KVW 4096   // words per K (or V) tile block

__global__ __launch_bounds__(256, 2) void attn_tc(
    const unsigned* __restrict__ qbuf, const unsigned* __restrict__ kbuf,
    const unsigned* __restrict__ vbuf, const int* __restrict__ mask,
    unsigned* __restrict__ ctx)
{
    extern __shared__ unsigned sm[];
    unsigned* Ksm = sm;                       // [2][4096]
    unsigned* Vsm = sm + 2 * KVW;             // [2][4096]
    unsigned* Pw  = sm + 4 * KVW;             // [8 warps][1024]
    int*      Mk  = (int*)(sm + 4 * KVW + 8192);  // [2][64]

    const int tid = threadIdx.x;
    const int lane = tid & 31, wid = tid >> 5;
    const int g = lane >> 2, tig = lane & 3;

    const int qt = blockIdx.x;
    const int h  = blockIdx.y;
    const int b  = blockIdx.z;
    const int bh = b * 16 + h;

    // ---- Q fragments direct from gmem ----
    const unsigned* qbase = qbuf + (((size_t)(bh * 16 + qt) * 8 + wid) * 8) * 128;
    uint4 qa[8];
#pragma unroll
    for (int ks = 0; ks < 8; ks++)
        qa[ks] = *(const uint4*)&qbase[ks * 128 + lane * 4];

    // K/V loaders: thread copies 16 words of each block
    const int off = tid * 16;
    const unsigned sk_base = sptr(&Ksm[off]);
    const unsigned sv_base = sptr(&Vsm[off]);
    const unsigned* kblk0 = kbuf + ((size_t)bh * 32) * KVW;
    const unsigned* vblk0 = vbuf + ((size_t)bh * 32) * KVW;

    // issue tile 0
    {
#pragma unroll
        for (int i = 0; i < 4; i++) cpa16(sk_base + i * 16, kblk0 + off + i * 4);
#pragma unroll
        for (int i = 0; i < 4; i++) cpa16(sv_base + i * 16, vblk0 + off + i * 4);
        if (tid < 16) cpa16(sptr(&Mk[tid * 4]), mask + b * 2048 + tid * 4);
        asm volatile("cp.async.commit_group;\n");
    }

    float O[8][4];
#pragma unroll
    for (int nt = 0; nt < 8; nt++)
#pragma unroll
        for (int i = 0; i < 4; i++) O[nt][i] = 0.0f;
    float mA = -1e30f, mB = -1e30f, lA = 0.0f, lB = 0.0f;

    unsigned* Pme = Pw + wid * 1024;

    for (int t = 0; t < 32; t++) {
        asm volatile("cp.async.wait_group 0;\n");
        __syncthreads();  // tile t visible; other buffer free (read finished at t-1)

        if (t + 1 < 32) {
            const int s = (t + 1) & 1;
            const unsigned* kg = kblk0 + (size_t)(t + 1) * KVW + off;
            const unsigned* vg = vblk0 + (size_t)(t + 1) * KVW + off;
            const unsigned sk = sk_base + s * (KVW * 4);
            const unsigned sv = sv_base + s * (KVW * 4);
#pragma unroll
            for (int i = 0; i < 4; i++) cpa16(sk + i * 16, kg + i * 4);
#pragma unroll
            for (int i = 0; i < 4; i++) cpa16(sv + i * 16, vg + i * 4);
            if (tid < 16) cpa16(sptr(&Mk[s * 64 + tid * 4]),
                                mask + b * 2048 + (t + 1) * 64 + tid * 4);
            asm volatile("cp.async.commit_group;\n");
        }

        const unsigned* Kb = Ksm + (t & 1) * KVW;
        const unsigned* Vb = Vsm + (t & 1) * KVW;
        const int*      Mb = Mk + (t & 1) * 64;

        // ---- S = Q K^T : B-frag LDS.64 ----
        float s[8][4];
#pragma unroll
        for (int nt = 0; nt < 8; nt++)
#pragma unroll
            for (int i = 0; i < 4; i++) s[nt][i] = 0.0f;

#pragma unroll
        for (int nt = 0; nt < 8; nt++) {
#pragma unroll
            for (int ks = 0; ks < 8; ks++) {
                uint2 bf = *(const uint2*)&Kb[(ks * 8 + nt) * 64 + lane * 2];
                mma_tf32(s[nt], (const unsigned*)&qa[ks], (const unsigned*)&bf);
            }
        }

        // ---- mask + online softmax ----
        float mxA = -1e30f, mxB = -1e30f;
#pragma unroll
        for (int nt = 0; nt < 8; nt++) {
            const int c = nt * 8 + 2 * tig;
            const int m0 = Mb[c], m1 = Mb[c + 1];
            s[nt][0] = (m0 == 0) ? NEGV : s[nt][0] * 0.125f;
            s[nt][1] = (m1 == 0) ? NEGV : s[nt][1] * 0.125f;
            s[nt][2] = (m0 == 0) ? NEGV : s[nt][2] * 0.125f;
            s[nt][3] = (m1 == 0) ? NEGV : s[nt][3] * 0.125f;
            mxA = fmaxf(mxA, fmaxf(s[nt][0], s[nt][1]));
            mxB = fmaxf(mxB, fmaxf(s[nt][2], s[nt][3]));
        }
        mxA = fmaxf(mxA, __shfl_xor_sync(0xffffffffu, mxA, 1));
        mxA = fmaxf(mxA, __shfl_xor_sync(0xffffffffu, mxA, 2));
        mxB = fmaxf(mxB, __shfl_xor_sync(0xffffffffu, mxB, 1));
        mxB = fmaxf(mxB, __shfl_xor_sync(0xffffffffu, mxB, 2));

        const float mnA = fmaxf(mA, mxA);
        const float mnB = fmaxf(mB, mxB);
        const float alphaA = __expf(mA - mnA);
        const float alphaB = __expf(mB - mnB);
        float sumA = 0.0f, sumB = 0.0f;
#pragma unroll
        for (int nt = 0; nt < 8; nt++) {
            s[nt][0] = __expf(s[nt][0] - mnA);
            s[nt][1] = __expf(s[nt][1] - mnA);
            s[nt][2] = __expf(s[nt][2] - mnB);
            s[nt][3] = __expf(s[nt][3] - mnB);
            sumA += s[nt][0] + s[nt][1];
            sumB += s[nt][2] + s[nt][3];
        }
        sumA += __shfl_xor_sync(0xffffffffu, sumA, 1);
        sumA += __shfl_xor_sync(0xffffffffu, sumA, 2);
        sumB += __shfl_xor_sync(0xffffffffu, sumB, 1);
        sumB += __shfl_xor_sync(0xffffffffu, sumB, 2);
        lA = lA * alphaA + sumA;  mA = mnA;
        lB = lB * alphaB + sumB;  mB = mnB;
#pragma unroll
        for (int nt = 0; nt < 8; nt++) {
            O[nt][0] *= alphaA; O[nt][1] *= alphaA;
            O[nt][2] *= alphaB; O[nt][3] *= alphaB;
        }

        // ---- P -> per-warp A-frag smem tile (STS.64 x16) ----
#pragma unroll
        for (int nt = 0; nt < 8; nt++) {
            const int d0 = 2 * tig, d1 = 2 * tig + 1;
            const int w0 = (g * 4 + (d0 & 3)) * 4 + ((d0 & 7) >> 2) * 2;
            const int w1 = (g * 4 + (d1 & 3)) * 4 + ((d1 & 7) >> 2) * 2;
            uint2 u0; u0.x = f2tf32(s[nt][0]); u0.y = f2tf32(s[nt][2]);
            uint2 u1; u1.x = f2tf32(s[nt][1]); u1.y = f2tf32(s[nt][3]);
            *(uint2*)&Pme[nt * 128 + w0] = u0;
            *(uint2*)&Pme[nt * 128 + w1] = u1;
        }
        __syncwarp();

        uint4 pa[8];
#pragma unroll
        for (int ks = 0; ks < 8; ks++)
            pa[ks] = *(const uint4*)&Pme[ks * 128 + lane * 4];

        // ---- O += P V : B-frag LDS.64 ----
#pragma unroll
        for (int nt = 0; nt < 8; nt++) {
#pragma unroll
            for (int ks = 0; ks < 8; ks++) {
                uint2 bf = *(const uint2*)&Vb[(ks * 8 + nt) * 64 + lane * 2];
                mma_tf32(O[nt], (const unsigned*)&pa[ks], (const unsigned*)&bf);
            }
        }
    }

    // epilogue: ctx in A-frag tile layout (Ct = 128) for gemm2
    const float invA = 1.0f / lA;
    const float invB = 1.0f / lB;
    const int mt = (b * 2048 + qt * 128 + wid * 16) >> 4;
#pragma unroll
    for (int nt = 0; nt < 8; nt++) {
        const int kt = h * 8 + nt;
        unsigned* tb = ctx + ((size_t)mt * 128 + kt) * 128;
        const int tig2 = 2 * tig;
        const int ik = tig2 >> 2, tp = tig2 & 3;
        uint2 w0, w1;
        w0.x = f2tf32(O[nt][0] * invA);
        w0.y = f2tf32(O[nt][2] * invB);
        w1.x = f2tf32(O[nt][1] * invA);
        w1.y = f2tf32(O[nt][3] * invB);
        *(uint2*)&tb[(g * 4 + tp) * 4 + ik * 2]     = w0;
        *(uint2*)&tb[(g * 4 + tp + 1) * 4 + ik * 2] = w1;
    }
}

// ---------------------------------------------------------------------------
extern "C" void kernel_launch(void* const* d_in, const int* in_sizes, int n_in,
                              void* d_out, int out_size)
{
    const float* qs   = (const float*)d_in[0];
    const int*   mask = (const int*)d_in[1];
    const float* Wqkv = (const float*)d_in[2];
    const float* Wout = (const float*)d_in[3];
    const float* bout = (const float*)d_in[4];
    float* out = (float*)d_out;

    unsigned *qP, *kP, *vP, *ctxP, *qsT, *wqkvT, *woutT;
    cudaGetSymbolAddress((void**)&qP,    g_q);
    cudaGetSymbolAddress((void**)&kP,    g_k);
    cudaGetSymbolAddress((void**)&vP,    g_v);
    cudaGetSymbolAddress((void**)&ctxP,  g_ctx);
    cudaGetSymbolAddress((void**)&qsT,   g_qsT);
    cudaGetSymbolAddress((void**)&wqkvT, g_wqkvT);
    cudaGetSymbolAddress((void**)&woutT, g_woutT);

    const int gemmSmem = 6 * STG_W * 4;  // 98304 B
    cudaFuncSetAttribute(sgemm_tf32,
                         cudaFuncAttributeMaxDynamicSharedMemorySize, gemmSmem);

    const int attnSmem = (4 * KVW + 8192 + 128) * 4;  // 98816 B
    cudaFuncSetAttribute(attn_tc,
                         cudaFuncAttributeMaxDynamicSharedMemorySize, attnSmem);

    // 0) pre-convert + permute inputs into fragment-major tf32 layouts
    permA_tf32<<<4096, 256>>>((const float4*)qs, qsT, 1024, 4096 * 1024 / 4);
    permB_tf32<<<3072, 256>>>((const float4*)Wqkv, wqkvT, 3072, 1024 * 3072 / 4);
    permB_tf32<<<1024, 256>>>((const float4*)Wout, woutT, 1024, 1024 * 1024 / 4);

    // 1) qkv = qs @ Wqkv, scattered into fragment-major Q/K/V buffers
    sgemm_tf32<<<dim3(24, 32), 256, gemmSmem>>>(
        qsT, wqkvT, nullptr, nullptr, qP, kP, vP, 4096, 3072, 1024, 1);

    // 2) fused masked attention -> ctx (A-frag layout)
    attn_tc<<<dim3(16, 16, 2), 256, attnSmem>>>(qP, kP, vP, mask, ctxP);

    // 3) out = ctx @ Wout + bout  (fp32 final)
    sgemm_tf32<<<dim3(8, 32), 256, gemmSmem>>>(
        ctxP, woutT, bout, out, nullptr, nullptr, nullptr, 4096, 1024, 1024, 0);
}

// round 11
// speedup vs baseline: 1.4428x; 1.0949x over previous
#include <cuda_runtime.h>

#define NEGV (-1000000000.0f)

// B=2 S=2048 D=1024 H=16 A=64
// Fragment-major tf32-bit buffers:
__device__ unsigned g_q[(size_t)4096 * 1024];     // A-frag per (b,h,qt,mt,kt)
__device__ unsigned g_k[(size_t)4096 * 1024];     // B-frag (n=key,k=dim)
__device__ unsigned g_v[(size_t)4096 * 1024];     // B-frag (n=dim,k=key)
__device__ unsigned g_ctx[(size_t)4096 * 1024];   // A-frag (gemm2 A)
__device__ unsigned g_qsT[(size_t)4096 * 1024];   // A-frag (gemm1 A)
__device__ unsigned g_wqkvT[(size_t)1024 * 3072]; // B-frag (gemm1 B)
__device__ unsigned g_woutT[(size_t)1024 * 1024]; // B-frag (gemm2 B)

__device__ __forceinline__ unsigned f2tf32(float x) {
    unsigned y;
    asm("cvt.rna.tf32.f32 %0, %1;" : "=r"(y) : "f"(x));
    return y;
}

__device__ __forceinline__ void mma_tf32(float* d, const unsigned* a, const unsigned* b) {
    asm volatile(
        "mma.sync.aligned.m16n8k8.row.col.f32.tf32.tf32.f32 "
        "{%0,%1,%2,%3}, {%4,%5,%6,%7}, {%8,%9}, {%0,%1,%2,%3};"
        : "+f"(d[0]), "+f"(d[1]), "+f"(d[2]), "+f"(d[3])
        : "r"(a[0]), "r"(a[1]), "r"(a[2]), "r"(a[3]), "r"(b[0]), "r"(b[1]));
}

__device__ __forceinline__ unsigned sptr(const void* p) {
    return (unsigned)__cvta_generic_to_shared(p);
}

__device__ __forceinline__ void cpa16(unsigned s, const void* g) {
    asm volatile("cp.async.cg.shared.global [%0], [%1], 16;\n" :: "r"(s), "l"(g));
}

// ---------------------------------------------------------------------------
// Input permutation kernels (round-8 proven)
// ---------------------------------------------------------------------------
__global__ __launch_bounds__(256) void permA_tf32(
    const float4* __restrict__ src, unsigned* __restrict__ dst,
    int C, int total4)
{
    int idx = blockIdx.x * 256 + threadIdx.x;
    if (idx >= total4) return;
    const int C4 = C >> 2;
    const int r = idx / C4;
    const int k = (idx - r * C4) * 4;
    float4 v = src[idx];
    const int Ct = C >> 3;
    const int mt = r >> 4, rm = r & 15;
    const int gp = rm & 7, im = rm >> 3;
    const int kt = k >> 3, ik = (k & 7) >> 2;
    unsigned* tb = dst + ((size_t)mt * Ct + kt) * 128 + ik * 2 + im;
    tb[(gp * 4 + 0) * 4] = f2tf32(v.x);
    tb[(gp * 4 + 1) * 4] = f2tf32(v.y);
    tb[(gp * 4 + 2) * 4] = f2tf32(v.z);
    tb[(gp * 4 + 3) * 4] = f2tf32(v.w);
}

__global__ __launch_bounds__(256) void permB_tf32(
    const float4* __restrict__ src, unsigned* __restrict__ dst,
    int N, int total4)
{
    int idx = blockIdx.x * 256 + threadIdx.x;
    if (idx >= total4) return;
    const int N4 = N >> 2;
    const int k = idx / N4;
    const int n = (idx - k * N4) * 4;
    float4 v = src[idx];
    const int Nt = N >> 3;
    const int kt = k >> 3, tg = k & 3, ik = (k & 7) >> 2;
    const int nt = n >> 3, g0 = n & 7;
    unsigned* tb = dst + ((size_t)kt * Nt + nt) * 64 + tg * 2 + ik;
    tb[(g0 + 0) * 8] = f2tf32(v.x);
    tb[(g0 + 1) * 8] = f2tf32(v.y);
    tb[(g0 + 2) * 8] = f2tf32(v.z);
    tb[(g0 + 3) * 8] = f2tf32(v.w);
}

// ---------------------------------------------------------------------------
// TF32 SGEMM on fragment-major operands.
// Round 11: 512 threads, 16 warps (4M x 4N), warp tile 32x32 -> 8 warps/SMSP.
// Same 128x128 block tile, BK=32, 3-stage cp.async ring, one barrier/iter.
// mode 0: fp32 C + bias.  mode 1: scatter qkv into g_q/g_k/g_v.
// ---------------------------------------------------------------------------
#define STG_W 4096

__global__ __launch_bounds__(512, 2) void sgemm_tf32(
    const unsigned* __restrict__ A, const unsigned* __restrict__ B,
    const float* __restrict__ bias, void* __restrict__ Cout,
    unsigned* __restrict__ qbuf, unsigned* __restrict__ kbuf,
    unsigned* __restrict__ vbuf,
    int M, int N, int K, int mode)
{
    extern __shared__ unsigned smg[];
    unsigned* As = smg;                 // [3][4096]
    unsigned* Bs = smg + 3 * STG_W;     // [3][4096]

    const int tid = threadIdx.x;
    const int bx = blockIdx.x, by = blockIdx.y;
    const int lane = tid & 31, wid = tid >> 5;
    const int g = lane >> 2, tig = lane & 3;
    const int wm = (wid & 3) * 32;      // 4 warps along M
    const int wn = (wid >> 2) * 32;     // 4 warps along N
    const int Ct = K >> 3;
    const int Nt = N >> 3;

    // loaders: 512 threads, 8 words each per operand per stage
    const int amt = tid >> 6;           // A m-tile 0..7 (64 threads each)
    const int aq  = (tid & 63) * 8;     // word offset in 512-word chunk
    const int bkt = tid >> 7;           // B k-tile 0..3 (128 threads each)
    const int bq  = (tid & 127) * 8;    // word offset in 1024-word chunk

    const unsigned* abase = A + ((size_t)(by * 8 + amt) * Ct) * 128 + aq;
    const unsigned* bbase = B + (size_t)bx * 16 * 64 + bq;

    const unsigned sa_base = sptr(&As[amt * 512 + aq]);
    const unsigned sb_base = sptr(&Bs[bkt * 1024 + bq]);

    float acc[2][4][4];
#pragma unroll
    for (int mt = 0; mt < 2; mt++)
#pragma unroll
        for (int nt = 0; nt < 4; nt++)
#pragma unroll
            for (int i = 0; i < 4; i++) acc[mt][nt][i] = 0.0f;

    const int nt_iters = K >> 5;

#pragma unroll
    for (int p = 0; p < 2; p++) {
        const unsigned* ag = abase + p * 4 * 128;
        const unsigned* bg = bbase + (size_t)(p * 4 + bkt) * Nt * 64;
        const unsigned sa = sa_base + p * (STG_W * 4);
        const unsigned sb = sb_base + p * (STG_W * 4);
#pragma unroll
        for (int i = 0; i < 2; i++) cpa16(sa + i * 16, ag + i * 4);
#pragma unroll
        for (int i = 0; i < 2; i++) cpa16(sb + i * 16, bg + i * 4);
        asm volatile("cp.async.commit_group;\n");
    }

    for (int t = 0; t < nt_iters; t++) {
        if (t + 1 < nt_iters)
            asm volatile("cp.async.wait_group 1;\n");
        else
            asm volatile("cp.async.wait_group 0;\n");
        __syncthreads();

        if (t + 2 < nt_iters) {
            const int s = (t + 2) % 3;
            const unsigned* ag = abase + (t + 2) * 4 * 128;
            const unsigned* bg = bbase + (size_t)((t + 2) * 4 + bkt) * Nt * 64;
            const unsigned sa = sa_base + s * (STG_W * 4);
            const unsigned sb = sb_base + s * (STG_W * 4);
#pragma unroll
            for (int i = 0; i < 2; i++) cpa16(sa + i * 16, ag + i * 4);
#pragma unroll
            for (int i = 0; i < 2; i++) cpa16(sb + i * 16, bg + i * 4);
        }
        asm volatile("cp.async.commit_group;\n");

        const unsigned* Ab = As + (t % 3) * STG_W;
        const unsigned* Bb = Bs + (t % 3) * STG_W;

#pragma unroll
        for (int ks = 0; ks < 4; ks++) {
            uint4 af[2];
            uint2 bf[4];
#pragma unroll
            for (int mt = 0; mt < 2; mt++)
                af[mt] = *(const uint4*)&Ab[(((wid & 3) * 2 + mt) * 4 + ks) * 128 + lane * 4];
#pragma unroll
            for (int nt = 0; nt < 4; nt++)
                bf[nt] = *(const uint2*)&Bb[(ks * 16 + (wid >> 2) * 4 + nt) * 64 + lane * 2];
#pragma unroll
            for (int mt = 0; mt < 2; mt++)
#pragma unroll
                for (int nt = 0; nt < 4; nt++)
                    mma_tf32(acc[mt][nt], (const unsigned*)&af[mt], (const unsigned*)&bf[nt]);
        }
    }

    if (mode == 1) {
        // scatter into fragment-major Q/K/V buffers (round-9 verified formulas)
#pragma unroll
        for (int mt = 0; mt < 2; mt++) {
            const int row = by * 128 + wm + mt * 16 + g;
            const int bb = row >> 11;
            const int s = row & 2047;
#pragma unroll
            for (int nt = 0; nt < 4; nt++) {
                const int col = bx * 128 + wn + nt * 8 + 2 * tig;
                unsigned v00 = f2tf32(acc[mt][nt][0]);
                unsigned v01 = f2tf32(acc[mt][nt][1]);
                unsigned v10 = f2tf32(acc[mt][nt][2]);
                unsigned v11 = f2tf32(acc[mt][nt][3]);
                if (col < 1024) {            // Q -> A-frag
                    const int h = col >> 6, d = col & 63;
                    const int bh = bb * 16 + h;
                    size_t base = (((size_t)(bh * 16 + (s >> 7)) * 8 + ((s & 127) >> 4)) * 8
                                   + (d >> 3)) * 128;
                    const int gq = s & 7;
                    const int w0 = (gq * 4 + (d & 3)) * 4 + ((d & 7) >> 2) * 2;
                    const int d1 = d + 1;
                    const int w1 = (gq * 4 + (d1 & 3)) * 4 + ((d1 & 7) >> 2) * 2;
                    uint2 u0; u0.x = v00; u0.y = v10;
                    uint2 u1; u1.x = v01; u1.y = v11;
                    *(uint2*)&qbuf[base + w0] = u0;
                    *(uint2*)&qbuf[base + w1] = u1;
                } else if (col < 2048) {     // K -> B-frag (n=key, k=dim)
                    const int h = (col - 1024) >> 6, d = (col - 1024) & 63;
                    const int bh = bb * 16 + h;
                    const int tt = s >> 6, key = s & 63;
                    unsigned* blk = kbuf + ((size_t)(bh * 32 + tt)) * 4096;
                    const int gk = key & 7;
                    const int tile0 = (d >> 3) * 8 + (key >> 3);
                    const int tile1 = (d >> 3) * 8 + ((key + 8) >> 3);
                    const int wd0 = (gk * 4 + (d & 3)) * 2 + ((d & 7) >> 2);
                    const int d1 = d + 1;
                    const int wd1 = (gk * 4 + (d1 & 3)) * 2 + ((d1 & 7) >> 2);
                    blk[tile0 * 64 + wd0] = v00;
                    blk[tile0 * 64 + wd1] = v01;
                    blk[tile1 * 64 + wd0] = v10;
                    blk[tile1 * 64 + wd1] = v11;
                } else {                     // V -> B-frag (n=dim, k=key)
                    const int h = (col - 2048) >> 6, d = (col - 2048) & 63;
                    const int bh = bb * 16 + h;
                    const int tt = s >> 6, key = s & 63;
                    unsigned* blk = vbuf + ((size_t)(bh * 32 + tt)) * 4096;
                    const int tigv = key & 3, ikv = (key & 7) >> 2;
                    const int tile0 = (key >> 3) * 8 + (d >> 3);
                    const int tile1 = ((key + 8) >> 3) * 8 + (d >> 3);
                    const int wv0 = ((d & 7) * 4 + tigv) * 2 + ikv;
                    const int d1 = d + 1;
                    const int wv1 = (((d1) & 7) * 4 + tigv) * 2 + ikv;
                    blk[tile0 * 64 + wv0] = v00;
                    blk[tile0 * 64 + wv1] = v01;
                    blk[tile1 * 64 + wv0] = v10;
                    blk[tile1 * 64 + wv1] = v11;
                }
            }
        }
    } else {
        float* C = (float*)Cout;
        float bv0[4], bv1[4];
#pragma unroll
        for (int nt = 0; nt < 4; nt++) {
            int col = bx * 128 + wn + nt * 8 + 2 * tig;
            bv0[nt] = bias ? bias[col] : 0.0f;
            bv1[nt] = bias ? bias[col + 1] : 0.0f;
        }
#pragma unroll
        for (int mt = 0; mt < 2; mt++) {
            int row = by * 128 + wm + mt * 16 + g;
#pragma unroll
            for (int nt = 0; nt < 4; nt++) {
                int col = bx * 128 + wn + nt * 8 + 2 * tig;
                float2 s0, s1;
                s0.x = acc[mt][nt][0] + bv0[nt];
                s0.y = acc[mt][nt][1] + bv1[nt];
                s1.x = acc[mt][nt][2] + bv0[nt];
                s1.y = acc[mt][nt][3] + bv1[nt];
                *(float2*)(C + (size_t)row * N + col) = s0;
                *(float2*)(C + (size_t)(row + 8) * N + col) = s1;
            }
        }
    }
}

// ---------------------------------------------------------------------------
// Fragment-major tensor-core flash attention (round-9 proven, unchanged).
// ---------------------------------------------------------------------------
#define KVW 4096

__global__ __launch_bounds__(256, 2) void attn_tc(
    const unsigned* __restrict__ qbuf, const unsigned* __restrict__ kbuf,
    const unsigned* __restrict__ vbuf, const int* __restrict__ mask,
    unsigned* __restrict__ ctx)
{
    extern __shared__ unsigned sm[];
    unsigned* Ksm = sm;                       // [2][4096]
    unsigned* Vsm = sm + 2 * KVW;             // [2][4096]
    unsigned* Pw  = sm + 4 * KVW;             // [8 warps][1024]
    int*      Mk  = (int*)(sm + 4 * KVW + 8192);  // [2][64]

    const int tid = threadIdx.x;
    const int lane = tid & 31, wid = tid >> 5;
    const int g = lane >> 2, tig = lane & 3;

    const int qt = blockIdx.x;
    const int h  = blockIdx.y;
    const int b  = blockIdx.z;
    const int bh = b * 16 + h;

    const unsigned* qbase = qbuf + (((size_t)(bh * 16 + qt) * 8 + wid) * 8) * 128;
    uint4 qa[8];
#pragma unroll
    for (int ks = 0; ks < 8; ks++)
        qa[ks] = *(const uint4*)&qbase[ks * 128 + lane * 4];

    const int off = tid * 16;
    const unsigned sk_base = sptr(&Ksm[off]);
    const unsigned sv_base = sptr(&Vsm[off]);
    const unsigned* kblk0 = kbuf + ((size_t)bh * 32) * KVW;
    const unsigned* vblk0 = vbuf + ((size_t)bh * 32) * KVW;

    {
#pragma unroll
        for (int i = 0; i < 4; i++) cpa16(sk_base + i * 16, kblk0 + off + i * 4);
#pragma unroll
        for (int i = 0; i < 4; i++) cpa16(sv_base + i * 16, vblk0 + off + i * 4);
        if (tid < 16) cpa16(sptr(&Mk[tid * 4]), mask + b * 2048 + tid * 4);
        asm volatile("cp.async.commit_group;\n");
    }

    float O[8][4];
#pragma unroll
    for (int nt = 0; nt < 8; nt++)
#pragma unroll
        for (int i = 0; i < 4; i++) O[nt][i] = 0.0f;
    float mA = -1e30f, mB = -1e30f, lA = 0.0f, lB = 0.0f;

    unsigned* Pme = Pw + wid * 1024;

    for (int t = 0; t < 32; t++) {
        asm volatile("cp.async.wait_group 0;\n");
        __syncthreads();

        if (t + 1 < 32) {
            const int s = (t + 1) & 1;
            const unsigned* kg = kblk0 + (size_t)(t + 1) * KVW + off;
            const unsigned* vg = vblk0 + (size_t)(t + 1) * KVW + off;
            const unsigned sk = sk_base + s * (KVW * 4);
            const unsigned sv = sv_base + s * (KVW * 4);
#pragma unroll
            for (int i = 0; i < 4; i++) cpa16(sk + i * 16, kg + i * 4);
#pragma unroll
            for (int i = 0; i < 4; i++) cpa16(sv + i * 16, vg + i * 4);
            if (tid < 16) cpa16(sptr(&Mk[s * 64 + tid * 4]),
                                mask + b * 2048 + (t + 1) * 64 + tid * 4);
            asm volatile("cp.async.commit_group;\n");
        }

        const unsigned* Kb = Ksm + (t & 1) * KVW;
        const unsigned* Vb = Vsm + (t & 1) * KVW;
        const int*      Mb = Mk + (t & 1) * 64;

        float s[8][4];
#pragma unroll
        for (int nt = 0; nt < 8; nt++)
#pragma unroll
            for (int i = 0; i < 4; i++) s[nt][i] = 0.0f;

#pragma unroll
        for (int nt = 0; nt < 8; nt++) {
#pragma unroll
            for (int ks = 0; ks < 8; ks++) {
                uint2 bf = *(const uint2*)&Kb[(ks * 8 + nt) * 64 + lane * 2];
                mma_tf32(s[nt], (const unsigned*)&qa[ks], (const unsigned*)&bf);
            }
        }

        float mxA = -1e30f, mxB = -1e30f;
#pragma unroll
        for (int nt = 0; nt < 8; nt++) {
            const int c = nt * 8 + 2 * tig;
            const int m0 = Mb[c], m1 = Mb[c + 1];
            s[nt][0] = (m0 == 0) ? NEGV : s[nt][0] * 0.125f;
            s[nt][1] = (m1 == 0) ? NEGV : s[nt][1] * 0.125f;
            s[nt][2] = (m0 == 0) ? NEGV : s[nt][2] * 0.125f;
            s[nt][3] = (m1 == 0) ? NEGV : s[nt][3] * 0.125f;
            mxA = fmaxf(mxA, fmaxf(s[nt][0], s[nt][1]));
            mxB = fmaxf(mxB, fmaxf(s[nt][2], s[nt][3]));
        }
        mxA = fmaxf(mxA, __shfl_xor_sync(0xffffffffu, mxA, 1));
        mxA = fmaxf(mxA, __shfl_xor_sync(0xffffffffu, mxA, 2));
        mxB = fmaxf(mxB, __shfl_xor_sync(0xffffffffu, mxB, 1));
        mxB = fmaxf(mxB, __shfl_xor_sync(0xffffffffu, mxB, 2));

        const float mnA = fmaxf(mA, mxA);
        const float mnB = fmaxf(mB, mxB);
        const float alphaA = __expf(mA - mnA);
        const float alphaB = __expf(mB - mnB);
        float sumA = 0.0f, sumB = 0.0f;
#pragma unroll
        for (int nt = 0; nt < 8; nt++) {
            s[nt][0] = __expf(s[nt][0] - mnA);
            s[nt][1] = __expf(s[nt][1] - mnA);
            s[nt][2] = __expf(s[nt][2] - mnB);
            s[nt][3] = __expf(s[nt][3] - mnB);
            sumA += s[nt][0] + s[nt][1];
            sumB += s[nt][2] + s[nt][3];
        }
        sumA += __shfl_xor_sync(0xffffffffu, sumA, 1);
        sumA += __shfl_xor_sync(0xffffffffu, sumA, 2);
        sumB += __shfl_xor_sync(0xffffffffu, sumB, 1);
        sumB += __shfl_xor_sync(0xffffffffu, sumB, 2);
        lA = lA * alphaA + sumA;  mA = mnA;
        lB = lB * alphaB + sumB;  mB = mnB;
#pragma unroll
        for (int nt = 0; nt < 8; nt++) {
            O[nt][0] *= alphaA; O[nt][1] *= alphaA;
            O[nt][2] *= alphaB; O[nt][3] *= alphaB;
        }

#pragma unroll
        for (int nt = 0; nt < 8; nt++) {
            const int d0 = 2 * tig, d1 = 2 * tig + 1;
            const int w0 = (g * 4 + (d0 & 3)) * 4 + ((d0 & 7) >> 2) * 2;
            const int w1 = (g * 4 + (d1 & 3)) * 4 + ((d1 & 7) >> 2) * 2;
            uint2 u0; u0.x = f2tf32(s[nt][0]); u0.y = f2tf32(s[nt][2]);
            uint2 u1; u1.x = f2tf32(s[nt][1]); u1.y = f2tf32(s[nt][3]);
            *(uint2*)&Pme[nt * 128 + w0] = u0;
            *(uint2*)&Pme[nt * 128 + w1] = u1;
        }
        __syncwarp();

        uint4 pa[8];
#pragma unroll
        for (int ks = 0; ks < 8; ks++)
            pa[ks] = *(const uint4*)&Pme[ks * 128 + lane * 4];

#pragma unroll
        for (int nt = 0; nt < 8; nt++) {
#pragma unroll
            for (int ks = 0; ks < 8; ks++) {
                uint2 bf = *(const uint2*)&Vb[(ks * 8 + nt) * 64 + lane * 2];
                mma_tf32(O[nt], (const unsigned*)&pa[ks], (const unsigned*)&bf);
            }
        }
    }

    // epilogue: ctx in A-frag tile layout (Ct = 128) for gemm2
    const float invA = 1.0f / lA;
    const float invB = 1.0f / lB;
    const int mt = (b * 2048 + qt * 128 + wid * 16) >> 4;
#pragma unroll
    for (int nt = 0; nt < 8; nt++) {
        const int kt = h * 8 + nt;
        unsigned* tb = ctx + ((size_t)mt * 128 + kt) * 128;
        const int tig2 = 2 * tig;
        const int ik = tig2 >> 2, tp = tig2 & 3;
        uint2 w0, w1;
        w0.x = f2tf32(O[nt][0] * invA);
        w0.y = f2tf32(O[nt][2] * invB);
        w1.x = f2tf32(O[nt][1] * invA);
        w1.y = f2tf32(O[nt][3] * invB);
        *(uint2*)&tb[(g * 4 + tp) * 4 + ik * 2]     = w0;
        *(uint2*)&tb[(g * 4 + tp + 1) * 4 + ik * 2] = w1;
    }
}

// ---------------------------------------------------------------------------
extern "C" void kernel_launch(void* const* d_in, const int* in_sizes, int n_in,
                              void* d_out, int out_size)
{
    const float* qs   = (const float*)d_in[0];
    const int*   mask = (const int*)d_in[1];
    const float* Wqkv = (const float*)d_in[2];
    const float* Wout = (const float*)d_in[3];
    const float* bout = (const float*)d_in[4];
    float* out = (float*)d_out;

    unsigned *qP, *kP, *vP, *ctxP, *qsT, *wqkvT, *woutT;
    cudaGetSymbolAddress((void**)&qP,    g_q);
    cudaGetSymbolAddress((void**)&kP,    g_k);
    cudaGetSymbolAddress((void**)&vP,    g_v);
    cudaGetSymbolAddress((void**)&ctxP,  g_ctx);
    cudaGetSymbolAddress((void**)&qsT,   g_qsT);
    cudaGetSymbolAddress((void**)&wqkvT, g_wqkvT);
    cudaGetSymbolAddress((void**)&woutT, g_woutT);

    const int gemmSmem = 6 * STG_W * 4;  // 98304 B
    cudaFuncSetAttribute(sgemm_tf32,
                         cudaFuncAttributeMaxDynamicSharedMemorySize, gemmSmem);

    const int attnSmem = (4 * KVW + 8192 + 128) * 4;  // 98816 B
    cudaFuncSetAttribute(attn_tc,
                         cudaFuncAttributeMaxDynamicSharedMemorySize, attnSmem);

    // 0) pre-convert + permute inputs into fragment-major tf32 layouts
    permA_tf32<<<4096, 256>>>((const float4*)qs, qsT, 1024, 4096 * 1024 / 4);
    permB_tf32<<<3072, 256>>>((const float4*)Wqkv, wqkvT, 3072, 1024 * 3072 / 4);
    permB_tf32<<<1024, 256>>>((const float4*)Wout, woutT, 1024, 1024 * 1024 / 4);

    // 1) qkv = qs @ Wqkv, scattered into fragment-major Q/K/V buffers
    sgemm_tf32<<<dim3(24, 32), 512, gemmSmem>>>(
        qsT, wqkvT, nullptr, nullptr, qP, kP, vP, 4096, 3072, 1024, 1);

    // 2) fused masked attention -> ctx (A-frag layout)
    attn_tc<<<dim3(16, 16, 2), 256, attnSmem>>>(qP, kP, vP, mask, ctxP);

    // 3) out = ctx @ Wout + bout  (fp32 final)
    sgemm_tf32<<<dim3(8, 32), 512, gemmSmem>>>(
        ctxP, woutT, bout, out, nullptr, nullptr, nullptr, 4096, 1024, 1024, 0);
}